// round 5
// baseline (speedup 1.0000x reference)
#include <cuda_runtime.h>
#include <cuda_fp16.h>
#include <mma.h>
#include <cstdint>

using namespace nvcuda;

#define NPOS  1008
#define KPAD  768
#define NCAP  288

// ---------------- device scratch ----------------
__device__ float  g_wavT[512 * 128];                // wavT[k][o]
__device__ __half g_B_E[256 * KPAD];                // E[c][tau], zero-padded tau>=752
__device__ __half g_Bpk[144 * 128 * 16];            // packed block-diag W per 2-cap group: [g][n][k]
__device__ float  g_P2[(size_t)4096 * 2304];        // p [b][flat=c*9+m]
__device__ __half g_UH[(size_t)4096 * 18432];       // u_hat [b][cap*64 + d*16 + o]

// ---------------- precompute kernels ----------------
__global__ void wav_kernel(const float* __restrict__ a, const float* __restrict__ w) {
    int o = blockIdx.x, k = threadIdx.x;
    float av = fmaxf(a[o], 1e-5f);
    float t  = fmaf((float)k, 2.0f / 511.0f, -1.0f);
    float ts = t / av;
    g_wavT[k * 128 + o] = cosf(w[o] * t) * expf(-0.5f * ts * ts);
}

__global__ void compose_kernel(const float* __restrict__ conv_w) {
    __shared__ float cwT[2048];             // [k2][o]
    int c = blockIdx.x;
    for (int i = threadIdx.x; i < 2048; i += blockDim.x) {
        int o = i >> 4, k2 = i & 15;
        cwT[k2 * 128 + o] = conv_w[c * 2048 + i];
    }
    __syncthreads();
    for (int tau = threadIdx.x; tau < KPAD; tau += blockDim.x) {
        float acc = 0.0f;
        if (tau < 752) {
            #pragma unroll
            for (int k2 = 0; k2 < 16; ++k2) {
                int k = tau - 16 * k2;
                if (k >= 0 && k < 512) {
                    const float4* wr = (const float4*)(g_wavT + k * 128);
                    const float4* cp = (const float4*)(cwT + k2 * 128);
                    #pragma unroll 8
                    for (int o4 = 0; o4 < 32; ++o4) {
                        float4 wv = wr[o4], cv = cp[o4];
                        acc = fmaf(cv.x, wv.x, acc);
                        acc = fmaf(cv.y, wv.y, acc);
                        acc = fmaf(cv.z, wv.z, acc);
                        acc = fmaf(cv.w, wv.w, acc);
                    }
                }
            }
        }
        g_B_E[c * KPAD + tau] = __float2half_rn(acc);
    }
}

// B_pk[g][n=capl*64+(d*16+o)][k=capk*8+i] = (capl==capk) ? W[(2g+capl)][d][o][i] : 0
__global__ void bpk_kernel(const float* __restrict__ Wc) {
    int i = blockIdx.x * 256 + threadIdx.x;          // 144*2048
    if (i >= 144 * 2048) return;
    int g = i >> 11, rem = i & 2047;
    int n = rem >> 4, k = rem & 15;
    int capl = n >> 6, np = n & 63;
    int capk = k >> 3, ii = k & 7;
    float v = (capl == capk) ? Wc[(size_t)(2 * g + capl) * 512 + np * 8 + ii] : 0.0f;
    g_Bpk[i] = __float2half_rn(v);
}

// ---------------- conv GEMM (wmma): P[36864,256] = im2col(x) x E^T ----------------
#define CONV_SMEM (36864 + 512)
__global__ __launch_bounds__(256, 2)
void conv_wmma_kernel(const float* __restrict__ x, const float* __restrict__ conv_b) {
    extern __shared__ char smem[];
    __half* As = (__half*)smem;
    __half* Bs = As + 128 * 72;
    float*  stage = (float*)smem;
    float*  bias  = (float*)(smem + 36864);

    const int tid = threadIdx.x;
    const int wid = tid >> 5;
    const int wm = wid & 3, wn = wid >> 2;
    const int r0 = blockIdx.x * 128;
    const int n0 = blockIdx.y * 128;

    if (tid < 128) bias[tid] = conv_b[n0 + tid];

    const int row = tid >> 1, seg = (tid & 1) * 32;
    const int r = r0 + row, ab = r / 9, am = r - 9 * ab;
    const float* xrow = x + (size_t)ab * NPOS + 32 * am;
    const __half* brow = g_B_E + (size_t)(n0 + row) * KPAD;

    wmma::fragment<wmma::matrix_a, 16, 16, 16, __half, wmma::row_major> af[2];
    wmma::fragment<wmma::matrix_b, 16, 16, 16, __half, wmma::col_major> bf[4];
    wmma::fragment<wmma::accumulator, 16, 16, 16, float> acc[2][4];
    #pragma unroll
    for (int i = 0; i < 2; ++i)
        #pragma unroll
        for (int j = 0; j < 4; ++j)
            wmma::fill_fragment(acc[i][j], 0.0f);

    for (int chunk = 0; chunk < 12; ++chunk) {
        {
            int kbase = chunk * 64 + seg;
            uint32_t hw[16];
            if (chunk < 11 || seg == 0) {
                const float4* xp = (const float4*)(xrow + kbase);
                #pragma unroll
                for (int q = 0; q < 8; ++q) {
                    float4 v = xp[q];
                    __half2_raw h0 = __half2_raw(__floats2half2_rn(v.x, v.y));
                    __half2_raw h1 = __half2_raw(__floats2half2_rn(v.z, v.w));
                    hw[2*q]   = h0.x | ((uint32_t)h0.y << 16);
                    hw[2*q+1] = h1.x | ((uint32_t)h1.y << 16);
                }
            } else {
                const float4* xp = (const float4*)(xrow + kbase);
                #pragma unroll
                for (int q = 0; q < 4; ++q) {
                    float4 v = xp[q];
                    __half2_raw h0 = __half2_raw(__floats2half2_rn(v.x, v.y));
                    __half2_raw h1 = __half2_raw(__floats2half2_rn(v.z, v.w));
                    hw[2*q]   = h0.x | ((uint32_t)h0.y << 16);
                    hw[2*q+1] = h1.x | ((uint32_t)h1.y << 16);
                }
                #pragma unroll
                for (int q = 8; q < 16; ++q) hw[q] = 0u;
            }
            uint2* ap = (uint2*)(As + row * 72 + seg);
            #pragma unroll
            for (int q = 0; q < 8; ++q) ap[q] = make_uint2(hw[2*q], hw[2*q+1]);
        }
        {
            const uint4* bp = (const uint4*)(brow + chunk * 64 + seg);
            uint2* dp = (uint2*)(Bs + row * 72 + seg);
            #pragma unroll
            for (int q = 0; q < 4; ++q) {
                uint4 v = bp[q];
                dp[2*q]   = make_uint2(v.x, v.y);
                dp[2*q+1] = make_uint2(v.z, v.w);
            }
        }
        __syncthreads();
        #pragma unroll
        for (int kk = 0; kk < 4; ++kk) {
            #pragma unroll
            for (int i = 0; i < 2; ++i)
                wmma::load_matrix_sync(af[i], As + (wm*32 + i*16) * 72 + kk*16, 72);
            #pragma unroll
            for (int j = 0; j < 4; ++j)
                wmma::load_matrix_sync(bf[j], Bs + (wn*64 + j*16) * 72 + kk*16, 72);
            #pragma unroll
            for (int i = 0; i < 2; ++i)
                #pragma unroll
                for (int j = 0; j < 4; ++j)
                    wmma::mma_sync(acc[i][j], af[i], bf[j], acc[i][j]);
        }
        __syncthreads();
    }

    const int b_first = r0 / 9;
    const int nb = (r0 + 127) / 9 - b_first + 1;
    for (int p = 0; p < 2; ++p) {
        if (wn == p) {
            #pragma unroll
            for (int i = 0; i < 2; ++i)
                #pragma unroll
                for (int j = 0; j < 4; ++j)
                    wmma::store_matrix_sync(stage + (wm*32 + i*16) * 68 + j*16,
                                            acc[i][j], 68, wmma::mem_row_major);
        }
        __syncthreads();
        for (int i = tid; i < nb * 64; i += 256) {
            int bl = i >> 6, col = i & 63;
            int b = b_first + bl;
            int c = n0 + p * 64 + col;
            float bv = bias[p * 64 + col];
            float* dst = g_P2 + (size_t)b * 2304 + c * 9;
            int rb = b * 9;
            #pragma unroll
            for (int m = 0; m < 9; ++m) {
                int rr = rb + m;
                if (rr >= r0 && rr < r0 + 128)
                    dst[m] = stage[(rr - r0) * 68 + col] + bv;
            }
        }
        __syncthreads();
    }
}

// ---------------- u_hat GEMM: D[128b x 128] = A[128x16] x Bpk[16x128], 2 caps/group ----------------
// smem: Aw 4KB | Bw 4KB | stage 128x128 f32 = 64KB
#define UHAT_SMEM (8192 + 65536)
__global__ __launch_bounds__(256, 2)
void uhat_gemm_kernel() {
    extern __shared__ char smem[];
    __half* Aw = (__half*)smem;                 // [128 rows][16 k] row-major
    __half* Bw = Aw + 2048;                     // [128 n][16 k] (col-major frag layout)
    float*  stage = (float*)(smem + 8192);      // [128][128]

    const int tid = threadIdx.x, wid = tid >> 5;
    const int b0 = blockIdx.x * 128;
    const int g  = blockIdx.y;                  // 0..143

    // ---- A build: squash 256 (b_l, capl) rows ----
    {
        int b_l = tid >> 1, capl = tid & 1;
        int b = b0 + b_l, cap = g * 2 + capl;
        const float4* pp = (const float4*)(g_P2 + (size_t)b * 2304 + cap * 8);
        float4 p0 = pp[0], p1 = pp[1];
        float sn = p0.x*p0.x + p0.y*p0.y + p0.z*p0.z + p0.w*p0.w
                 + p1.x*p1.x + p1.y*p1.y + p1.z*p1.z + p1.w*p1.w;
        float sc = (sn / (1.0f + sn)) * rsqrtf(sn + 1e-8f);
        __half2_raw h0 = __half2_raw(__floats2half2_rn(p0.x*sc, p0.y*sc));
        __half2_raw h1 = __half2_raw(__floats2half2_rn(p0.z*sc, p0.w*sc));
        __half2_raw h2 = __half2_raw(__floats2half2_rn(p1.x*sc, p1.y*sc));
        __half2_raw h3 = __half2_raw(__floats2half2_rn(p1.z*sc, p1.w*sc));
        *(uint4*)(Aw + b_l * 16 + capl * 8) =
            make_uint4(h0.x | ((uint32_t)h0.y << 16), h1.x | ((uint32_t)h1.y << 16),
                       h2.x | ((uint32_t)h2.y << 16), h3.x | ((uint32_t)h3.y << 16));
    }
    // ---- B load (4KB) ----
    ((uint4*)Bw)[tid] = ((const uint4*)(g_Bpk + (size_t)g * 2048))[tid];
    __syncthreads();

    // ---- MMA: warp w owns rows w*16..w*16+15, all 128 n ----
    {
        wmma::fragment<wmma::matrix_a, 16, 16, 16, __half, wmma::row_major> af;
        wmma::load_matrix_sync(af, Aw + wid * 16 * 16, 16);
        #pragma unroll
        for (int j = 0; j < 8; ++j) {
            wmma::fragment<wmma::matrix_b, 16, 16, 16, __half, wmma::col_major> bfj;
            wmma::load_matrix_sync(bfj, Bw + j * 16 * 16, 16);
            wmma::fragment<wmma::accumulator, 16, 16, 16, float> acc;
            wmma::fill_fragment(acc, 0.0f);
            wmma::mma_sync(acc, af, bfj, acc);
            wmma::store_matrix_sync(stage + (wid * 16) * 128 + j * 16, acc, 128,
                                    wmma::mem_row_major);
        }
    }
    __syncthreads();

    // ---- write 128 rows x 128 halves (256B/row contiguous) ----
    {
        int row = tid >> 1, cs = (tid & 1) * 64;
        const float4* sp = (const float4*)(stage + row * 128 + cs);
        uint4* dp = (uint4*)(g_UH + (size_t)(b0 + row) * 18432 + g * 128 + cs);
        #pragma unroll
        for (int u = 0; u < 8; ++u) {
            float4 v0 = sp[2*u], v1 = sp[2*u + 1];
            __half2_raw a0 = __half2_raw(__floats2half2_rn(v0.x, v0.y));
            __half2_raw a1 = __half2_raw(__floats2half2_rn(v0.z, v0.w));
            __half2_raw a2 = __half2_raw(__floats2half2_rn(v1.x, v1.y));
            __half2_raw a3 = __half2_raw(__floats2half2_rn(v1.z, v1.w));
            dp[u] = make_uint4(a0.x | ((uint32_t)a0.y << 16), a1.x | ((uint32_t)a1.y << 16),
                               a2.x | ((uint32_t)a2.y << 16), a3.x | ((uint32_t)a3.y << 16));
        }
    }
}

// ---------------- routing: 1 sample per CTA ----------------
#define ROUT_FLOATS (18720 + 1152 + 1152 + 256 + 64 + 64 + 4)
#define ROUT_SMEM   (ROUT_FLOATS * 4)
__global__ __launch_bounds__(256, 2)
void routing_kernel(float* __restrict__ out, int nB) {
    extern __shared__ float sm[];
    float* uh   = sm;              // [288][65]
    float* bij  = sm + 18720;
    float* cij  = bij + 1152;
    float* part = cij + 1152;
    float* sjv  = part + 256;
    float* vv   = sjv + 64;
    float* snd  = vv + 64;
    const int tid = threadIdx.x;
    const int b = blockIdx.x;

    const uint4* src = (const uint4*)(g_UH + (size_t)b * 18432);
    #pragma unroll
    for (int it = 0; it < 9; ++it) {
        int vi = tid + it * 256;
        uint4 v = src[vi];
        int cc = vi >> 3, o0 = (vi & 7) * 8;
        float* d = uh + cc * 65 + o0;
        __half2* h = (__half2*)&v;
        #pragma unroll
        for (int e = 0; e < 4; ++e) {
            float2 f = __half22float2(h[e]);
            d[2*e] = f.x; d[2*e+1] = f.y;
        }
    }
    for (int i = tid; i < 1152; i += 256) bij[i] = 0.0f;
    __syncthreads();

    for (int r = 0; r < 3; ++r) {
        for (int j = tid; j < NCAP; j += 256) {
            float b0 = bij[j*4+0], b1 = bij[j*4+1], b2 = bij[j*4+2], b3 = bij[j*4+3];
            float mx = fmaxf(fmaxf(b0, b1), fmaxf(b2, b3));
            float e0 = expf(b0-mx), e1 = expf(b1-mx), e2 = expf(b2-mx), e3 = expf(b3-mx);
            float inv = 1.0f / (e0 + e1 + e2 + e3);
            cij[j*4+0] = e0*inv; cij[j*4+1] = e1*inv; cij[j*4+2] = e2*inv; cij[j*4+3] = e3*inv;
        }
        __syncthreads();
        {
            int o64 = tid & 63, prt = tid >> 6, d = o64 >> 4;
            float a2 = 0.0f;
            int cb = prt * 72;
            for (int cc = cb; cc < cb + 72; ++cc)
                a2 += cij[cc * 4 + d] * uh[cc * 65 + o64];
            part[prt * 64 + o64] = a2;
        }
        __syncthreads();
        if (tid < 64)
            sjv[tid] = part[tid] + part[tid+64] + part[tid+128] + part[tid+192];
        __syncthreads();
        if (tid < 4) {
            float sn = 0.0f;
            #pragma unroll
            for (int o = 0; o < 16; ++o) { float t = sjv[tid*16+o]; sn += t*t; }
            snd[tid] = (sn / (1.0f + sn)) * rsqrtf(sn + 1e-8f);
        }
        __syncthreads();
        if (tid < 64) vv[tid] = sjv[tid] * snd[tid >> 4];
        __syncthreads();
        if (r < 2) {
            for (int i = tid; i < 1152; i += 256) {
                int cc = i >> 2, d2 = i & 3;
                const float* up = uh + cc * 65 + d2 * 16;
                const float* vp = vv + d2 * 16;
                float agr = 0.0f;
                #pragma unroll
                for (int o = 0; o < 16; ++o) agr += up[o] * vp[o];
                bij[i] += agr;
            }
            __syncthreads();
        }
    }
    if (tid < 4) {
        float sn = 0.0f;
        #pragma unroll
        for (int o = 0; o < 16; ++o) { float t = vv[tid*16+o]; sn += t*t; }
        out[b * 4 + tid] = sqrtf(sn);
    }
    float* out_cij = out + (size_t)nB * 4 + (size_t)b * 1152;
    for (int i = tid; i < 1152; i += 256) out_cij[i] = cij[i];
}

// ---------------- launcher ----------------
extern "C" void kernel_launch(void* const* d_in, const int* in_sizes, int n_in,
                              void* d_out, int out_size) {
    const float* x      = (const float*)d_in[0];
    const float* a      = (const float*)d_in[1];
    const float* w      = (const float*)d_in[2];
    const float* conv_w = (const float*)d_in[3];
    const float* conv_b = (const float*)d_in[4];
    const float* W_caps = (const float*)d_in[5];
    int nB = in_sizes[0] / NPOS;   // 4096

    cudaFuncSetAttribute(uhat_gemm_kernel, cudaFuncAttributeMaxDynamicSharedMemorySize, UHAT_SMEM);
    cudaFuncSetAttribute(routing_kernel,   cudaFuncAttributeMaxDynamicSharedMemorySize, ROUT_SMEM);

    wav_kernel<<<128, 512>>>(a, w);
    compose_kernel<<<256, 256>>>(conv_w);
    bpk_kernel<<<(144 * 2048 + 255) / 256, 256>>>(W_caps);
    conv_wmma_kernel<<<dim3(nB * 9 / 128, 2), 256, CONV_SMEM>>>(x, conv_b);
    uhat_gemm_kernel<<<dim3(nB / 128, 144), 256, UHAT_SMEM>>>();
    routing_kernel<<<nB, 256, ROUT_SMEM>>>((float*)d_out, nB);
}

// round 6
// speedup vs baseline: 1.9787x; 1.9787x over previous
#include <cuda_runtime.h>
#include <cuda_fp16.h>
#include <mma.h>
#include <cstdint>

using namespace nvcuda;

#define NPOS  1008
#define KPAD  768
#define NCAP  288

// ---------------- device scratch ----------------
__device__ float  g_wavT[512 * 128];                // wavT[k][o]
__device__ __half g_cwhf[256 * 2048];               // conv_w fp16, k-index = o + 128*k2
__device__ __half g_W2T[768 * 2048];                // wav im2col: [tau][o + 128*k2]
__device__ __half g_B_E[256 * KPAD];                // E[c][tau]
__device__ __half g_Bpk[144 * 128 * 16];            // packed block-diag W per 2-cap group: [g][n][k]
__device__ float  g_P2[(size_t)4096 * 2304];        // p [b][flat=c*9+m]
__device__ __half g_UH[(size_t)4096 * 18432];       // u_hat [b][cap*64 + d*16 + o]

// ---------------- precompute kernels ----------------
__global__ void wav_kernel(const float* __restrict__ a, const float* __restrict__ w) {
    int o = blockIdx.x, k = threadIdx.x;
    float av = fmaxf(a[o], 1e-5f);
    float t  = fmaf((float)k, 2.0f / 511.0f, -1.0f);
    float ts = t / av;
    g_wavT[k * 128 + o] = cosf(w[o] * t) * expf(-0.5f * ts * ts);
}

__global__ void cwhf_kernel(const float* __restrict__ conv_w) {
    int i = blockIdx.x * 256 + threadIdx.x;          // 256*2048
    if (i >= 256 * 2048) return;
    int c = i >> 11, j = i & 2047;
    int o = j & 127, k2 = j >> 7;
    g_cwhf[i] = __float2half_rn(conv_w[c * 2048 + o * 16 + k2]);
}

__global__ void w2t_kernel() {
    int i = blockIdx.x * 256 + threadIdx.x;          // 768*2048
    if (i >= 768 * 2048) return;
    int tau = i >> 11, j = i & 2047;
    int o = j & 127, k2 = j >> 7;
    int k = tau - 16 * k2;
    float v = (k >= 0 && k < 512) ? g_wavT[k * 128 + o] : 0.0f;
    g_W2T[i] = __float2half_rn(v);
}

// B_pk[g][n=capl*64+(d*16+o)][k=capk*8+i] = (capl==capk) ? W[(2g+capl)][d][o][i] : 0
__global__ void bpk_kernel(const float* __restrict__ Wc) {
    int i = blockIdx.x * 256 + threadIdx.x;          // 144*2048
    if (i >= 144 * 2048) return;
    int g = i >> 11, rem = i & 2047;
    int n = rem >> 4, k = rem & 15;
    int capl = n >> 6, np = n & 63;
    int capk = k >> 3, ii = k & 7;
    float v = (capl == capk) ? Wc[(size_t)(2 * g + capl) * 512 + np * 8 + ii] : 0.0f;
    g_Bpk[i] = __float2half_rn(v);
}

// ---------------- compose GEMM (wmma): E[256,768] = cwhf x W2T^T, K=2048 ----------------
#define COMP_SMEM 36864
__global__ __launch_bounds__(256, 2)
void compose_wmma_kernel() {
    extern __shared__ char smem[];
    __half* As = (__half*)smem;            // [128][72]
    __half* Bs = As + 128 * 72;
    float*  stage = (float*)smem;          // reuse: [128][68]

    const int tid = threadIdx.x;
    const int wid = tid >> 5;
    const int wm = wid & 3, wn = wid >> 2;
    const int c0   = blockIdx.x * 128;
    const int tau0 = blockIdx.y * 128;

    const int row = tid >> 1, seg = (tid & 1) * 32;
    const __half* arow = g_cwhf + (size_t)(c0 + row) * 2048;
    const __half* brow = g_W2T + (size_t)(tau0 + row) * 2048;

    wmma::fragment<wmma::matrix_a, 16, 16, 16, __half, wmma::row_major> af[2];
    wmma::fragment<wmma::matrix_b, 16, 16, 16, __half, wmma::col_major> bf[4];
    wmma::fragment<wmma::accumulator, 16, 16, 16, float> acc[2][4];
    #pragma unroll
    for (int i = 0; i < 2; ++i)
        #pragma unroll
        for (int j = 0; j < 4; ++j)
            wmma::fill_fragment(acc[i][j], 0.0f);

    for (int chunk = 0; chunk < 32; ++chunk) {
        {
            const uint4* ap = (const uint4*)(arow + chunk * 64 + seg);
            uint4* dp = (uint4*)(As + row * 72 + seg);
            #pragma unroll
            for (int q = 0; q < 4; ++q) dp[q] = ap[q];
        }
        {
            const uint4* bp = (const uint4*)(brow + chunk * 64 + seg);
            uint4* dp = (uint4*)(Bs + row * 72 + seg);
            #pragma unroll
            for (int q = 0; q < 4; ++q) dp[q] = bp[q];
        }
        __syncthreads();
        #pragma unroll
        for (int kk = 0; kk < 4; ++kk) {
            #pragma unroll
            for (int i = 0; i < 2; ++i)
                wmma::load_matrix_sync(af[i], As + (wm*32 + i*16) * 72 + kk*16, 72);
            #pragma unroll
            for (int j = 0; j < 4; ++j)
                wmma::load_matrix_sync(bf[j], Bs + (wn*64 + j*16) * 72 + kk*16, 72);
            #pragma unroll
            for (int i = 0; i < 2; ++i)
                #pragma unroll
                for (int j = 0; j < 4; ++j)
                    wmma::mma_sync(acc[i][j], af[i], bf[j], acc[i][j]);
        }
        __syncthreads();
    }

    for (int p = 0; p < 2; ++p) {
        if (wn == p) {
            #pragma unroll
            for (int i = 0; i < 2; ++i)
                #pragma unroll
                for (int j = 0; j < 4; ++j)
                    wmma::store_matrix_sync(stage + (wm*32 + i*16) * 68 + j*16,
                                            acc[i][j], 68, wmma::mem_row_major);
        }
        __syncthreads();
        {
            int r2 = tid >> 1, cs = (tid & 1) * 32;
            const float* sp = stage + r2 * 68 + cs;
            uint4 ov[4];
            #pragma unroll
            for (int u = 0; u < 4; ++u) {
                uint32_t pk[4];
                #pragma unroll
                for (int e = 0; e < 4; ++e) {
                    __half2_raw h = __half2_raw(__floats2half2_rn(sp[u*8 + 2*e], sp[u*8 + 2*e + 1]));
                    pk[e] = h.x | ((uint32_t)h.y << 16);
                }
                ov[u] = make_uint4(pk[0], pk[1], pk[2], pk[3]);
            }
            uint4* dp = (uint4*)(g_B_E + (size_t)(c0 + r2) * KPAD + tau0 + p * 64 + cs);
            #pragma unroll
            for (int u = 0; u < 4; ++u) dp[u] = ov[u];
        }
        __syncthreads();
    }
}

// ---------------- conv GEMM (wmma): P[36864,256] = im2col(x) x E^T ----------------
#define CONV_SMEM (36864 + 512)
__global__ __launch_bounds__(256, 2)
void conv_wmma_kernel(const float* __restrict__ x, const float* __restrict__ conv_b) {
    extern __shared__ char smem[];
    __half* As = (__half*)smem;
    __half* Bs = As + 128 * 72;
    float*  stage = (float*)smem;
    float*  bias  = (float*)(smem + 36864);

    const int tid = threadIdx.x;
    const int wid = tid >> 5;
    const int wm = wid & 3, wn = wid >> 2;
    const int r0 = blockIdx.x * 128;
    const int n0 = blockIdx.y * 128;

    if (tid < 128) bias[tid] = conv_b[n0 + tid];

    const int row = tid >> 1, seg = (tid & 1) * 32;
    const int r = r0 + row, ab = r / 9, am = r - 9 * ab;
    const float* xrow = x + (size_t)ab * NPOS + 32 * am;
    const __half* brow = g_B_E + (size_t)(n0 + row) * KPAD;

    wmma::fragment<wmma::matrix_a, 16, 16, 16, __half, wmma::row_major> af[2];
    wmma::fragment<wmma::matrix_b, 16, 16, 16, __half, wmma::col_major> bf[4];
    wmma::fragment<wmma::accumulator, 16, 16, 16, float> acc[2][4];
    #pragma unroll
    for (int i = 0; i < 2; ++i)
        #pragma unroll
        for (int j = 0; j < 4; ++j)
            wmma::fill_fragment(acc[i][j], 0.0f);

    for (int chunk = 0; chunk < 12; ++chunk) {
        {
            int kbase = chunk * 64 + seg;
            uint32_t hw[16];
            if (chunk < 11 || seg == 0) {
                const float4* xp = (const float4*)(xrow + kbase);
                #pragma unroll
                for (int q = 0; q < 8; ++q) {
                    float4 v = xp[q];
                    __half2_raw h0 = __half2_raw(__floats2half2_rn(v.x, v.y));
                    __half2_raw h1 = __half2_raw(__floats2half2_rn(v.z, v.w));
                    hw[2*q]   = h0.x | ((uint32_t)h0.y << 16);
                    hw[2*q+1] = h1.x | ((uint32_t)h1.y << 16);
                }
            } else {
                const float4* xp = (const float4*)(xrow + kbase);
                #pragma unroll
                for (int q = 0; q < 4; ++q) {
                    float4 v = xp[q];
                    __half2_raw h0 = __half2_raw(__floats2half2_rn(v.x, v.y));
                    __half2_raw h1 = __half2_raw(__floats2half2_rn(v.z, v.w));
                    hw[2*q]   = h0.x | ((uint32_t)h0.y << 16);
                    hw[2*q+1] = h1.x | ((uint32_t)h1.y << 16);
                }
                #pragma unroll
                for (int q = 8; q < 16; ++q) hw[q] = 0u;
            }
            uint2* ap = (uint2*)(As + row * 72 + seg);
            #pragma unroll
            for (int q = 0; q < 8; ++q) ap[q] = make_uint2(hw[2*q], hw[2*q+1]);
        }
        {
            const uint4* bp = (const uint4*)(brow + chunk * 64 + seg);
            uint2* dp = (uint2*)(Bs + row * 72 + seg);
            #pragma unroll
            for (int q = 0; q < 4; ++q) {
                uint4 v = bp[q];
                dp[2*q]   = make_uint2(v.x, v.y);
                dp[2*q+1] = make_uint2(v.z, v.w);
            }
        }
        __syncthreads();
        #pragma unroll
        for (int kk = 0; kk < 4; ++kk) {
            #pragma unroll
            for (int i = 0; i < 2; ++i)
                wmma::load_matrix_sync(af[i], As + (wm*32 + i*16) * 72 + kk*16, 72);
            #pragma unroll
            for (int j = 0; j < 4; ++j)
                wmma::load_matrix_sync(bf[j], Bs + (wn*64 + j*16) * 72 + kk*16, 72);
            #pragma unroll
            for (int i = 0; i < 2; ++i)
                #pragma unroll
                for (int j = 0; j < 4; ++j)
                    wmma::mma_sync(acc[i][j], af[i], bf[j], acc[i][j]);
        }
        __syncthreads();
    }

    const int b_first = r0 / 9;
    const int nb = (r0 + 127) / 9 - b_first + 1;
    for (int p = 0; p < 2; ++p) {
        if (wn == p) {
            #pragma unroll
            for (int i = 0; i < 2; ++i)
                #pragma unroll
                for (int j = 0; j < 4; ++j)
                    wmma::store_matrix_sync(stage + (wm*32 + i*16) * 68 + j*16,
                                            acc[i][j], 68, wmma::mem_row_major);
        }
        __syncthreads();
        for (int i = tid; i < nb * 64; i += 256) {
            int bl = i >> 6, col = i & 63;
            int b = b_first + bl;
            int c = n0 + p * 64 + col;
            float bv = bias[p * 64 + col];
            float* dst = g_P2 + (size_t)b * 2304 + c * 9;
            int rb = b * 9;
            #pragma unroll
            for (int m = 0; m < 9; ++m) {
                int rr = rb + m;
                if (rr >= r0 && rr < r0 + 128)
                    dst[m] = stage[(rr - r0) * 68 + col] + bv;
            }
        }
        __syncthreads();
    }
}

// ---------------- u_hat GEMM v3: padded frags, per-warp mini-stage, coalesced out ----------------
// smem: Aw[128][24] 6144B | Bw[128][24] 6144B | stage 8x[16][20]f 10240B
#define UHAT_SMEM (6144 + 6144 + 10240)
__global__ __launch_bounds__(256, 6)
void uhat_gemm_kernel() {
    extern __shared__ char smem[];
    __half* Aw = (__half*)smem;                  // [128][24]
    __half* Bw = (__half*)(smem + 6144);         // [128][24]
    float*  stg = (float*)(smem + 12288);        // per-warp [16][20]

    const int tid = threadIdx.x, wid = tid >> 5, lane = tid & 31;
    const int b0 = blockIdx.x * 128;
    const int g  = blockIdx.y;                   // 0..143

    // ---- A build: squash 256 (b_l, capl) rows into padded Aw ----
    {
        int b_l = tid >> 1, capl = tid & 1;
        int b = b0 + b_l, cap = g * 2 + capl;
        const float4* pp = (const float4*)(g_P2 + (size_t)b * 2304 + cap * 8);
        float4 p0 = pp[0], p1 = pp[1];
        float sn = p0.x*p0.x + p0.y*p0.y + p0.z*p0.z + p0.w*p0.w
                 + p1.x*p1.x + p1.y*p1.y + p1.z*p1.z + p1.w*p1.w;
        float sc = (sn / (1.0f + sn)) * rsqrtf(sn + 1e-8f);
        __half2_raw h0 = __half2_raw(__floats2half2_rn(p0.x*sc, p0.y*sc));
        __half2_raw h1 = __half2_raw(__floats2half2_rn(p0.z*sc, p0.w*sc));
        __half2_raw h2 = __half2_raw(__floats2half2_rn(p1.x*sc, p1.y*sc));
        __half2_raw h3 = __half2_raw(__floats2half2_rn(p1.z*sc, p1.w*sc));
        *(uint4*)(Aw + b_l * 24 + capl * 8) =
            make_uint4(h0.x | ((uint32_t)h0.y << 16), h1.x | ((uint32_t)h1.y << 16),
                       h2.x | ((uint32_t)h2.y << 16), h3.x | ((uint32_t)h3.y << 16));
    }
    // ---- B load into padded Bw ----
    {
        int n = tid >> 1, hseg = (tid & 1) * 8;
        uint4 v = *(const uint4*)(g_Bpk + (size_t)g * 2048 + n * 16 + hseg);
        *(uint4*)(Bw + n * 24 + hseg) = v;
    }
    __syncthreads();

    wmma::fragment<wmma::matrix_a, 16, 16, 16, __half, wmma::row_major> af;
    wmma::load_matrix_sync(af, Aw + wid * 16 * 24, 24);
    float* ws = stg + wid * 320;
    const int orow = lane >> 1, ocs = (lane & 1) * 8;
    #pragma unroll
    for (int j = 0; j < 8; ++j) {
        wmma::fragment<wmma::matrix_b, 16, 16, 16, __half, wmma::col_major> bfj;
        wmma::load_matrix_sync(bfj, Bw + j * 16 * 24, 24);
        wmma::fragment<wmma::accumulator, 16, 16, 16, float> acc;
        wmma::fill_fragment(acc, 0.0f);
        wmma::mma_sync(acc, af, bfj, acc);
        wmma::store_matrix_sync(ws, acc, 20, wmma::mem_row_major);
        __syncwarp();
        {
            const float* sp = ws + orow * 20 + ocs;
            uint32_t pk[4];
            #pragma unroll
            for (int e = 0; e < 4; ++e) {
                __half2_raw h = __half2_raw(__floats2half2_rn(sp[2*e], sp[2*e + 1]));
                pk[e] = h.x | ((uint32_t)h.y << 16);
            }
            *(uint4*)(g_UH + (size_t)(b0 + wid * 16 + orow) * 18432 + g * 128 + j * 16 + ocs) =
                make_uint4(pk[0], pk[1], pk[2], pk[3]);
        }
        __syncwarp();
    }
}

// ---------------- routing v2: fp16 u_hat in smem, occ 4 ----------------
// smem: uhh[288][72]h = 41472B | bij 4608 | cij 4608 | part 1024 | sjv 256 | vv 256 | snd 16
#define ROUT_SMEM (41472 + 4608 + 4608 + 1024 + 256 + 256 + 16)
__global__ __launch_bounds__(256, 4)
void routing_kernel(float* __restrict__ out, int nB) {
    extern __shared__ char smc[];
    __half* uhh = (__half*)smc;                  // [288][72]
    float* bij  = (float*)(smc + 41472);         // [1152]
    float* cij  = bij + 1152;
    float* part = cij + 1152;                    // [256]
    float* sjv  = part + 256;                    // [64]
    float* vv   = sjv + 64;                      // [64]
    float* snd  = vv + 64;                       // [4]
    const int tid = threadIdx.x;
    const int b = blockIdx.x;

    const uint4* src = (const uint4*)(g_UH + (size_t)b * 18432);
    #pragma unroll
    for (int it = 0; it < 9; ++it) {
        int vi = tid + it * 256;                 // 2304 uint4
        uint4 v = src[vi];
        int cc = vi >> 3, seg = (vi & 7) * 8;
        *(uint4*)(uhh + cc * 72 + seg) = v;
    }
    for (int i = tid; i < 1152; i += 256) bij[i] = 0.0f;
    __syncthreads();

    for (int r = 0; r < 3; ++r) {
        for (int j = tid; j < NCAP; j += 256) {
            float b0 = bij[j*4+0], b1 = bij[j*4+1], b2 = bij[j*4+2], b3 = bij[j*4+3];
            float mx = fmaxf(fmaxf(b0, b1), fmaxf(b2, b3));
            float e0 = expf(b0-mx), e1 = expf(b1-mx), e2 = expf(b2-mx), e3 = expf(b3-mx);
            float inv = 1.0f / (e0 + e1 + e2 + e3);
            cij[j*4+0] = e0*inv; cij[j*4+1] = e1*inv; cij[j*4+2] = e2*inv; cij[j*4+3] = e3*inv;
        }
        __syncthreads();
        {
            int o64 = tid & 63, prt = tid >> 6, d = o64 >> 4;
            float a2 = 0.0f;
            int cb = prt * 72;
            for (int cc = cb; cc < cb + 72; ++cc)
                a2 += cij[cc * 4 + d] * __half2float(uhh[cc * 72 + o64]);
            part[prt * 64 + o64] = a2;
        }
        __syncthreads();
        if (tid < 64)
            sjv[tid] = part[tid] + part[tid+64] + part[tid+128] + part[tid+192];
        __syncthreads();
        if (tid < 4) {
            float sn = 0.0f;
            #pragma unroll
            for (int o = 0; o < 16; ++o) { float t = sjv[tid*16+o]; sn += t*t; }
            snd[tid] = (sn / (1.0f + sn)) * rsqrtf(sn + 1e-8f);
        }
        __syncthreads();
        if (tid < 64) vv[tid] = sjv[tid] * snd[tid >> 4];
        __syncthreads();
        if (r < 2) {
            for (int i = tid; i < 1152; i += 256) {
                int cc = i >> 2, d2 = i & 3;
                const __half2* up = (const __half2*)(uhh + cc * 72 + d2 * 16);
                const float* vp = vv + d2 * 16;
                float agr = 0.0f;
                #pragma unroll
                for (int e = 0; e < 8; ++e) {
                    float2 f = __half22float2(up[e]);
                    agr += f.x * vp[2*e] + f.y * vp[2*e + 1];
                }
                bij[i] += agr;
            }
            __syncthreads();
        }
    }
    if (tid < 4) {
        float sn = 0.0f;
        #pragma unroll
        for (int o = 0; o < 16; ++o) { float t = vv[tid*16+o]; sn += t*t; }
        out[b * 4 + tid] = sqrtf(sn);
    }
    float* out_cij = out + (size_t)nB * 4 + (size_t)b * 1152;
    for (int i = tid; i < 1152; i += 256) out_cij[i] = cij[i];
}

// ---------------- launcher ----------------
extern "C" void kernel_launch(void* const* d_in, const int* in_sizes, int n_in,
                              void* d_out, int out_size) {
    const float* x      = (const float*)d_in[0];
    const float* a      = (const float*)d_in[1];
    const float* w      = (const float*)d_in[2];
    const float* conv_w = (const float*)d_in[3];
    const float* conv_b = (const float*)d_in[4];
    const float* W_caps = (const float*)d_in[5];
    int nB = in_sizes[0] / NPOS;   // 4096

    cudaFuncSetAttribute(routing_kernel, cudaFuncAttributeMaxDynamicSharedMemorySize, ROUT_SMEM);

    wav_kernel<<<128, 512>>>(a, w);
    cwhf_kernel<<<(256 * 2048 + 255) / 256, 256>>>(conv_w);
    w2t_kernel<<<(768 * 2048 + 255) / 256, 256>>>();
    bpk_kernel<<<(144 * 2048 + 255) / 256, 256>>>(W_caps);
    compose_wmma_kernel<<<dim3(2, 6), 256, COMP_SMEM>>>();
    conv_wmma_kernel<<<dim3(nB * 9 / 128, 2), 256, CONV_SMEM>>>(x, conv_b);
    uhat_gemm_kernel<<<dim3(nB / 128, 144), 256, UHAT_SMEM>>>();
    routing_kernel<<<nB, 256, ROUT_SMEM>>>((float*)d_out, nB);
}

// round 7
// speedup vs baseline: 2.0798x; 1.0511x over previous
#include <cuda_runtime.h>
#include <cuda_fp16.h>
#include <mma.h>
#include <cstdint>

using namespace nvcuda;

#define NPOS  1008
#define KPAD  768
#define NCAP  288

// ---------------- device scratch ----------------
__device__ float  g_wavT[512 * 128];                // wavT[k][o]
__device__ __half g_xhf[(size_t)4096 * 1024];       // x fp16, padded stride 1024 (tail zero)
__device__ __half g_cwhf[256 * 2048];               // conv_w fp16, k-index = o + 128*k2
__device__ __half g_W2T[768 * 2048];                // wav im2col: [tau][o + 128*k2]
__device__ __half g_B_E[256 * KPAD];                // E[c][tau]
__device__ __half g_Bpk[144 * 128 * 16];            // packed block-diag W: [g][n][k]
__device__ float  g_P2[(size_t)4096 * 2304];        // p [b][flat=c*9+m]
__device__ __half g_UH[(size_t)4096 * 18432];       // u_hat [b][cap*64 + d*16 + o]

// ---------------- precompute kernels ----------------
__global__ void wav_kernel(const float* __restrict__ a, const float* __restrict__ w) {
    int o = blockIdx.x, k = threadIdx.x;
    float av = fmaxf(a[o], 1e-5f);
    float t  = fmaf((float)k, 2.0f / 511.0f, -1.0f);
    float ts = t / av;
    g_wavT[k * 128 + o] = cosf(w[o] * t) * expf(-0.5f * ts * ts);
}

__global__ void xhf_kernel(const float* __restrict__ x) {
    size_t i = (size_t)blockIdx.x * 256 + threadIdx.x;   // 4096*1024 elems
    int b = (int)(i >> 10), pos = (int)(i & 1023);
    float v = (pos < NPOS) ? x[(size_t)b * NPOS + pos] : 0.0f;
    g_xhf[i] = __float2half_rn(v);
}

__global__ void cwhf_kernel(const float* __restrict__ conv_w) {
    int i = blockIdx.x * 256 + threadIdx.x;
    if (i >= 256 * 2048) return;
    int c = i >> 11, j = i & 2047;
    int o = j & 127, k2 = j >> 7;
    g_cwhf[i] = __float2half_rn(conv_w[c * 2048 + o * 16 + k2]);
}

__global__ void w2t_kernel() {
    int i = blockIdx.x * 256 + threadIdx.x;
    if (i >= 768 * 2048) return;
    int tau = i >> 11, j = i & 2047;
    int o = j & 127, k2 = j >> 7;
    int k = tau - 16 * k2;
    float v = (k >= 0 && k < 512) ? g_wavT[k * 128 + o] : 0.0f;
    g_W2T[i] = __float2half_rn(v);
}

__global__ void bpk_kernel(const float* __restrict__ Wc) {
    int i = blockIdx.x * 256 + threadIdx.x;
    if (i >= 144 * 2048) return;
    int g = i >> 11, rem = i & 2047;
    int n = rem >> 4, k = rem & 15;
    int capl = n >> 6, np = n & 63;
    int capk = k >> 3, ii = k & 7;
    float v = (capl == capk) ? Wc[(size_t)(2 * g + capl) * 512 + np * 8 + ii] : 0.0f;
    g_Bpk[i] = __float2half_rn(v);
}

// ---------------- compose GEMM (wmma): E[256,768] = cwhf x W2T^T, K=2048 ----------------
#define COMP_SMEM 36864
__global__ __launch_bounds__(256, 2)
void compose_wmma_kernel() {
    extern __shared__ char smem[];
    __half* As = (__half*)smem;
    __half* Bs = As + 128 * 72;
    float*  stage = (float*)smem;

    const int tid = threadIdx.x;
    const int wid = tid >> 5;
    const int wm = wid & 3, wn = wid >> 2;
    const int c0   = blockIdx.x * 128;
    const int tau0 = blockIdx.y * 128;

    const int row = tid >> 1, seg = (tid & 1) * 32;
    const __half* arow = g_cwhf + (size_t)(c0 + row) * 2048;
    const __half* brow = g_W2T + (size_t)(tau0 + row) * 2048;

    wmma::fragment<wmma::matrix_a, 16, 16, 16, __half, wmma::row_major> af[2];
    wmma::fragment<wmma::matrix_b, 16, 16, 16, __half, wmma::col_major> bf[4];
    wmma::fragment<wmma::accumulator, 16, 16, 16, float> acc[2][4];
    #pragma unroll
    for (int i = 0; i < 2; ++i)
        #pragma unroll
        for (int j = 0; j < 4; ++j)
            wmma::fill_fragment(acc[i][j], 0.0f);

    for (int chunk = 0; chunk < 32; ++chunk) {
        {
            const uint4* ap = (const uint4*)(arow + chunk * 64 + seg);
            uint4* dp = (uint4*)(As + row * 72 + seg);
            #pragma unroll
            for (int q = 0; q < 4; ++q) dp[q] = ap[q];
        }
        {
            const uint4* bp = (const uint4*)(brow + chunk * 64 + seg);
            uint4* dp = (uint4*)(Bs + row * 72 + seg);
            #pragma unroll
            for (int q = 0; q < 4; ++q) dp[q] = bp[q];
        }
        __syncthreads();
        #pragma unroll
        for (int kk = 0; kk < 4; ++kk) {
            #pragma unroll
            for (int i = 0; i < 2; ++i)
                wmma::load_matrix_sync(af[i], As + (wm*32 + i*16) * 72 + kk*16, 72);
            #pragma unroll
            for (int j = 0; j < 4; ++j)
                wmma::load_matrix_sync(bf[j], Bs + (wn*64 + j*16) * 72 + kk*16, 72);
            #pragma unroll
            for (int i = 0; i < 2; ++i)
                #pragma unroll
                for (int j = 0; j < 4; ++j)
                    wmma::mma_sync(acc[i][j], af[i], bf[j], acc[i][j]);
        }
        __syncthreads();
    }

    for (int p = 0; p < 2; ++p) {
        if (wn == p) {
            #pragma unroll
            for (int i = 0; i < 2; ++i)
                #pragma unroll
                for (int j = 0; j < 4; ++j)
                    wmma::store_matrix_sync(stage + (wm*32 + i*16) * 68 + j*16,
                                            acc[i][j], 68, wmma::mem_row_major);
        }
        __syncthreads();
        {
            int r2 = tid >> 1, cs = (tid & 1) * 32;
            const float* sp = stage + r2 * 68 + cs;
            uint4 ov[4];
            #pragma unroll
            for (int u = 0; u < 4; ++u) {
                uint32_t pk[4];
                #pragma unroll
                for (int e = 0; e < 4; ++e) {
                    __half2_raw h = __half2_raw(__floats2half2_rn(sp[u*8 + 2*e], sp[u*8 + 2*e + 1]));
                    pk[e] = h.x | ((uint32_t)h.y << 16);
                }
                ov[u] = make_uint4(pk[0], pk[1], pk[2], pk[3]);
            }
            uint4* dp = (uint4*)(g_B_E + (size_t)(c0 + r2) * KPAD + tau0 + p * 64 + cs);
            #pragma unroll
            for (int u = 0; u < 4; ++u) dp[u] = ov[u];
        }
        __syncthreads();
    }
}

// ---------------- conv GEMM (wmma): P[36864,256] = im2col(xhf) x E^T ----------------
#define CONV_SMEM (36864 + 512)
__global__ __launch_bounds__(256, 2)
void conv_wmma_kernel(const float* __restrict__ conv_b) {
    extern __shared__ char smem[];
    __half* As = (__half*)smem;
    __half* Bs = As + 128 * 72;
    float*  stage = (float*)smem;
    float*  bias  = (float*)(smem + 36864);

    const int tid = threadIdx.x;
    const int wid = tid >> 5;
    const int wm = wid & 3, wn = wid >> 2;
    const int r0 = blockIdx.x * 128;
    const int n0 = blockIdx.y * 128;

    if (tid < 128) bias[tid] = conv_b[n0 + tid];

    const int row = tid >> 1, seg = (tid & 1) * 32;
    const int r = r0 + row, ab = r / 9, am = r - 9 * ab;
    const __half* xrow = g_xhf + (size_t)ab * 1024 + 32 * am;   // padded; tail reads zeros
    const __half* brow = g_B_E + (size_t)(n0 + row) * KPAD;

    wmma::fragment<wmma::matrix_a, 16, 16, 16, __half, wmma::row_major> af[2];
    wmma::fragment<wmma::matrix_b, 16, 16, 16, __half, wmma::col_major> bf[4];
    wmma::fragment<wmma::accumulator, 16, 16, 16, float> acc[2][4];
    #pragma unroll
    for (int i = 0; i < 2; ++i)
        #pragma unroll
        for (int j = 0; j < 4; ++j)
            wmma::fill_fragment(acc[i][j], 0.0f);

    for (int chunk = 0; chunk < 12; ++chunk) {
        {
            const uint4* ap = (const uint4*)(xrow + chunk * 64 + seg);
            uint4* dp = (uint4*)(As + row * 72 + seg);
            #pragma unroll
            for (int q = 0; q < 4; ++q) dp[q] = ap[q];
        }
        {
            const uint4* bp = (const uint4*)(brow + chunk * 64 + seg);
            uint4* dp = (uint4*)(Bs + row * 72 + seg);
            #pragma unroll
            for (int q = 0; q < 4; ++q) dp[q] = bp[q];
        }
        __syncthreads();
        #pragma unroll
        for (int kk = 0; kk < 4; ++kk) {
            #pragma unroll
            for (int i = 0; i < 2; ++i)
                wmma::load_matrix_sync(af[i], As + (wm*32 + i*16) * 72 + kk*16, 72);
            #pragma unroll
            for (int j = 0; j < 4; ++j)
                wmma::load_matrix_sync(bf[j], Bs + (wn*64 + j*16) * 72 + kk*16, 72);
            #pragma unroll
            for (int i = 0; i < 2; ++i)
                #pragma unroll
                for (int j = 0; j < 4; ++j)
                    wmma::mma_sync(acc[i][j], af[i], bf[j], acc[i][j]);
        }
        __syncthreads();
    }

    const int b_first = r0 / 9;
    const int nb = (r0 + 127) / 9 - b_first + 1;
    for (int p = 0; p < 2; ++p) {
        if (wn == p) {
            #pragma unroll
            for (int i = 0; i < 2; ++i)
                #pragma unroll
                for (int j = 0; j < 4; ++j)
                    wmma::store_matrix_sync(stage + (wm*32 + i*16) * 68 + j*16,
                                            acc[i][j], 68, wmma::mem_row_major);
        }
        __syncthreads();
        for (int i = tid; i < nb * 64; i += 256) {
            int bl = i >> 6, col = i & 63;
            int b = b_first + bl;
            int c = n0 + p * 64 + col;
            float bv = bias[p * 64 + col];
            float* dst = g_P2 + (size_t)b * 2304 + c * 9;
            int rb = b * 9;
            #pragma unroll
            for (int m = 0; m < 9; ++m) {
                int rr = rb + m;
                if (rr >= r0 && rr < r0 + 128)
                    dst[m] = stage[(rr - r0) * 68 + col] + bv;
            }
        }
        __syncthreads();
    }
}

// ---------------- u_hat GEMM v3 ----------------
#define UHAT_SMEM (6144 + 6144 + 10240)
__global__ __launch_bounds__(256, 6)
void uhat_gemm_kernel() {
    extern __shared__ char smem[];
    __half* Aw = (__half*)smem;                  // [128][24]
    __half* Bw = (__half*)(smem + 6144);         // [128][24]
    float*  stg = (float*)(smem + 12288);        // per-warp [16][20]

    const int tid = threadIdx.x, wid = tid >> 5, lane = tid & 31;
    const int b0 = blockIdx.x * 128;
    const int g  = blockIdx.y;

    {
        int b_l = tid >> 1, capl = tid & 1;
        int b = b0 + b_l, cap = g * 2 + capl;
        const float4* pp = (const float4*)(g_P2 + (size_t)b * 2304 + cap * 8);
        float4 p0 = pp[0], p1 = pp[1];
        float sn = p0.x*p0.x + p0.y*p0.y + p0.z*p0.z + p0.w*p0.w
                 + p1.x*p1.x + p1.y*p1.y + p1.z*p1.z + p1.w*p1.w;
        float sc = (sn / (1.0f + sn)) * rsqrtf(sn + 1e-8f);
        __half2_raw h0 = __half2_raw(__floats2half2_rn(p0.x*sc, p0.y*sc));
        __half2_raw h1 = __half2_raw(__floats2half2_rn(p0.z*sc, p0.w*sc));
        __half2_raw h2 = __half2_raw(__floats2half2_rn(p1.x*sc, p1.y*sc));
        __half2_raw h3 = __half2_raw(__floats2half2_rn(p1.z*sc, p1.w*sc));
        *(uint4*)(Aw + b_l * 24 + capl * 8) =
            make_uint4(h0.x | ((uint32_t)h0.y << 16), h1.x | ((uint32_t)h1.y << 16),
                       h2.x | ((uint32_t)h2.y << 16), h3.x | ((uint32_t)h3.y << 16));
    }
    {
        int n = tid >> 1, hseg = (tid & 1) * 8;
        uint4 v = *(const uint4*)(g_Bpk + (size_t)g * 2048 + n * 16 + hseg);
        *(uint4*)(Bw + n * 24 + hseg) = v;
    }
    __syncthreads();

    wmma::fragment<wmma::matrix_a, 16, 16, 16, __half, wmma::row_major> af;
    wmma::load_matrix_sync(af, Aw + wid * 16 * 24, 24);
    float* ws = stg + wid * 320;
    const int orow = lane >> 1, ocs = (lane & 1) * 8;
    #pragma unroll
    for (int j = 0; j < 8; ++j) {
        wmma::fragment<wmma::matrix_b, 16, 16, 16, __half, wmma::col_major> bfj;
        wmma::load_matrix_sync(bfj, Bw + j * 16 * 24, 24);
        wmma::fragment<wmma::accumulator, 16, 16, 16, float> acc;
        wmma::fill_fragment(acc, 0.0f);
        wmma::mma_sync(acc, af, bfj, acc);
        wmma::store_matrix_sync(ws, acc, 20, wmma::mem_row_major);
        __syncwarp();
        {
            const float* sp = ws + orow * 20 + ocs;
            uint32_t pk[4];
            #pragma unroll
            for (int e = 0; e < 4; ++e) {
                __half2_raw h = __half2_raw(__floats2half2_rn(sp[2*e], sp[2*e + 1]));
                pk[e] = h.x | ((uint32_t)h.y << 16);
            }
            *(uint4*)(g_UH + (size_t)(b0 + wid * 16 + orow) * 18432 + g * 128 + j * 16 + ocs) =
                make_uint4(pk[0], pk[1], pk[2], pk[3]);
        }
        __syncwarp();
    }
}

// ---------------- routing v3: fp16 smem u_hat, r=0 fast path ----------------
#define ROUT_SMEM (41472 + 4608 + 4608 + 1024 + 256 + 256 + 16)
__global__ __launch_bounds__(256, 4)
void routing_kernel(float* __restrict__ out, int nB) {
    extern __shared__ char smc[];
    __half* uhh = (__half*)smc;                  // [288][72]
    float* bij  = (float*)(smc + 41472);         // [1152]
    float* cij  = bij + 1152;
    float* part = cij + 1152;                    // [256]
    float* sjv  = part + 256;                    // [64]
    float* vv   = sjv + 64;                      // [64]
    float* snd  = vv + 64;                       // [4]
    const int tid = threadIdx.x;
    const int b = blockIdx.x;

    const uint4* src = (const uint4*)(g_UH + (size_t)b * 18432);
    #pragma unroll
    for (int it = 0; it < 9; ++it) {
        int vi = tid + it * 256;
        uint4 v = src[vi];
        int cc = vi >> 3, seg = (vi & 7) * 8;
        *(uint4*)(uhh + cc * 72 + seg) = v;
    }
    __syncthreads();

    for (int r = 0; r < 3; ++r) {
        if (r > 0) {
            for (int j = tid; j < NCAP; j += 256) {
                float b0 = bij[j*4+0], b1 = bij[j*4+1], b2 = bij[j*4+2], b3 = bij[j*4+3];
                float mx = fmaxf(fmaxf(b0, b1), fmaxf(b2, b3));
                float e0 = expf(b0-mx), e1 = expf(b1-mx), e2 = expf(b2-mx), e3 = expf(b3-mx);
                float inv = 1.0f / (e0 + e1 + e2 + e3);
                cij[j*4+0] = e0*inv; cij[j*4+1] = e1*inv; cij[j*4+2] = e2*inv; cij[j*4+3] = e3*inv;
            }
            __syncthreads();
        }
        {
            int o64 = tid & 63, prt = tid >> 6, d = o64 >> 4;
            float a2 = 0.0f;
            int cb = prt * 72;
            if (r == 0) {
                for (int cc = cb; cc < cb + 72; ++cc)
                    a2 += __half2float(uhh[cc * 72 + o64]);
                a2 *= 0.25f;
            } else {
                for (int cc = cb; cc < cb + 72; ++cc)
                    a2 += cij[cc * 4 + d] * __half2float(uhh[cc * 72 + o64]);
            }
            part[prt * 64 + o64] = a2;
        }
        __syncthreads();
        if (tid < 64)
            sjv[tid] = part[tid] + part[tid+64] + part[tid+128] + part[tid+192];
        __syncthreads();
        if (tid < 4) {
            float sn = 0.0f;
            #pragma unroll
            for (int o = 0; o < 16; ++o) { float t = sjv[tid*16+o]; sn += t*t; }
            snd[tid] = (sn / (1.0f + sn)) * rsqrtf(sn + 1e-8f);
        }
        __syncthreads();
        if (tid < 64) vv[tid] = sjv[tid] * snd[tid >> 4];
        __syncthreads();
        if (r < 2) {
            for (int i = tid; i < 1152; i += 256) {
                int cc = i >> 2, d2 = i & 3;
                const __half2* up = (const __half2*)(uhh + cc * 72 + d2 * 16);
                const float* vp = vv + d2 * 16;
                float agr = 0.0f;
                #pragma unroll
                for (int e = 0; e < 8; ++e) {
                    float2 f = __half22float2(up[e]);
                    agr += f.x * vp[2*e] + f.y * vp[2*e + 1];
                }
                if (r == 0) bij[i] = agr; else bij[i] += agr;
            }
            __syncthreads();
        }
    }
    if (tid < 4) {
        float sn = 0.0f;
        #pragma unroll
        for (int o = 0; o < 16; ++o) { float t = vv[tid*16+o]; sn += t*t; }
        out[b * 4 + tid] = sqrtf(sn);
    }
    float* out_cij = out + (size_t)nB * 4 + (size_t)b * 1152;
    for (int i = tid; i < 1152; i += 256) out_cij[i] = cij[i];
}

// ---------------- launcher ----------------
extern "C" void kernel_launch(void* const* d_in, const int* in_sizes, int n_in,
                              void* d_out, int out_size) {
    const float* x      = (const float*)d_in[0];
    const float* a      = (const float*)d_in[1];
    const float* w      = (const float*)d_in[2];
    const float* conv_w = (const float*)d_in[3];
    const float* conv_b = (const float*)d_in[4];
    const float* W_caps = (const float*)d_in[5];
    int nB = in_sizes[0] / NPOS;   // 4096

    cudaFuncSetAttribute(routing_kernel, cudaFuncAttributeMaxDynamicSharedMemorySize, ROUT_SMEM);

    wav_kernel<<<128, 512>>>(a, w);
    xhf_kernel<<<(int)(((size_t)nB * 1024) / 256), 256>>>(x);
    cwhf_kernel<<<(256 * 2048 + 255) / 256, 256>>>(conv_w);
    w2t_kernel<<<(768 * 2048 + 255) / 256, 256>>>();
    bpk_kernel<<<(144 * 2048 + 255) / 256, 256>>>(W_caps);
    compose_wmma_kernel<<<dim3(2, 6), 256, COMP_SMEM>>>();
    conv_wmma_kernel<<<dim3(nB * 9 / 128, 2), 256, CONV_SMEM>>>(conv_b);
    uhat_gemm_kernel<<<dim3(nB / 128, 144), 256, UHAT_SMEM>>>();
    routing_kernel<<<nB, 256, ROUT_SMEM>>>((float*)d_out, nB);
}

// round 8
// speedup vs baseline: 2.1333x; 1.0258x over previous
#include <cuda_runtime.h>
#include <cuda_fp16.h>
#include <mma.h>
#include <cstdint>

using namespace nvcuda;

#define NPOS  1008
#define KPAD  768
#define NCAP  288

// ---------------- device scratch ----------------
__device__ float  g_wavT[512 * 128];                // wavT[k][o]
__device__ __half g_xhf[(size_t)4096 * 1024];       // x fp16, padded stride 1024 (tail zero)
__device__ __half g_cwhf[256 * 2048];               // conv_w fp16, k-index = o + 128*k2
__device__ __half g_W2T[768 * 2048];                // wav im2col: [tau][o + 128*k2]
__device__ __half g_B_E[256 * KPAD];                // E[c][tau]
__device__ __half g_Bpk[144 * 128 * 16];            // packed block-diag W: [g][n][k]
__device__ float  g_P2[(size_t)4096 * 2304];        // p [b][flat=c*9+m]
__device__ __half g_UH[(size_t)4096 * 18432];       // u_hat [b][cap*64 + d*16 + o]

// ---------------- helpers ----------------
static __device__ __forceinline__ uint32_t smem_u32(const void* p) {
    uint32_t a;
    asm("{ .reg .u64 t; cvta.to.shared.u64 t, %1; cvt.u32.u64 %0, t; }" : "=r"(a) : "l"(p));
    return a;
}
static __device__ __forceinline__ void cp_async16(uint32_t dst, const void* src) {
    asm volatile("cp.async.cg.shared.global [%0], [%1], 16;" :: "r"(dst), "l"(src));
}
#define CP_COMMIT() asm volatile("cp.async.commit_group;" ::: "memory")
#define CP_WAIT(n)  asm volatile("cp.async.wait_group %0;" :: "n"(n) : "memory")

// ---------------- precompute kernels ----------------
__global__ void wav_kernel(const float* __restrict__ a, const float* __restrict__ w) {
    int o = blockIdx.x, k = threadIdx.x;
    float av = fmaxf(a[o], 1e-5f);
    float t  = fmaf((float)k, 2.0f / 511.0f, -1.0f);
    float ts = t / av;
    g_wavT[k * 128 + o] = cosf(w[o] * t) * expf(-0.5f * ts * ts);
}

__global__ void xhf_kernel(const float* __restrict__ x) {
    size_t i = (size_t)blockIdx.x * 256 + threadIdx.x;
    int b = (int)(i >> 10), pos = (int)(i & 1023);
    float v = (pos < NPOS) ? x[(size_t)b * NPOS + pos] : 0.0f;
    g_xhf[i] = __float2half_rn(v);
}

__global__ void cwhf_kernel(const float* __restrict__ conv_w) {
    int i = blockIdx.x * 256 + threadIdx.x;
    if (i >= 256 * 2048) return;
    int c = i >> 11, j = i & 2047;
    int o = j & 127, k2 = j >> 7;
    g_cwhf[i] = __float2half_rn(conv_w[c * 2048 + o * 16 + k2]);
}

__global__ void w2t_kernel() {
    int i = blockIdx.x * 256 + threadIdx.x;
    if (i >= 768 * 2048) return;
    int tau = i >> 11, j = i & 2047;
    int o = j & 127, k2 = j >> 7;
    int k = tau - 16 * k2;
    float v = (k >= 0 && k < 512) ? g_wavT[k * 128 + o] : 0.0f;
    g_W2T[i] = __float2half_rn(v);
}

__global__ void bpk_kernel(const float* __restrict__ Wc) {
    int i = blockIdx.x * 256 + threadIdx.x;
    if (i >= 144 * 2048) return;
    int g = i >> 11, rem = i & 2047;
    int n = rem >> 4, k = rem & 15;
    int capl = n >> 6, np = n & 63;
    int capk = k >> 3, ii = k & 7;
    float v = (capl == capk) ? Wc[(size_t)(2 * g + capl) * 512 + np * 8 + ii] : 0.0f;
    g_Bpk[i] = __float2half_rn(v);
}

// ---------------- compose GEMM (wmma): E[256,768] = cwhf x W2T^T, K=2048 ----------------
#define COMP_SMEM 36864
__global__ __launch_bounds__(256, 2)
void compose_wmma_kernel() {
    extern __shared__ char smem[];
    __half* As = (__half*)smem;
    __half* Bs = As + 128 * 72;
    float*  stage = (float*)smem;

    const int tid = threadIdx.x;
    const int wid = tid >> 5;
    const int wm = wid & 3, wn = wid >> 2;
    const int c0   = blockIdx.x * 128;
    const int tau0 = blockIdx.y * 128;

    const int row = tid >> 1, seg = (tid & 1) * 32;
    const __half* arow = g_cwhf + (size_t)(c0 + row) * 2048;
    const __half* brow = g_W2T + (size_t)(tau0 + row) * 2048;

    wmma::fragment<wmma::matrix_a, 16, 16, 16, __half, wmma::row_major> af[2];
    wmma::fragment<wmma::matrix_b, 16, 16, 16, __half, wmma::col_major> bf[4];
    wmma::fragment<wmma::accumulator, 16, 16, 16, float> acc[2][4];
    #pragma unroll
    for (int i = 0; i < 2; ++i)
        #pragma unroll
        for (int j = 0; j < 4; ++j)
            wmma::fill_fragment(acc[i][j], 0.0f);

    for (int chunk = 0; chunk < 32; ++chunk) {
        {
            const uint4* ap = (const uint4*)(arow + chunk * 64 + seg);
            uint4* dp = (uint4*)(As + row * 72 + seg);
            #pragma unroll
            for (int q = 0; q < 4; ++q) dp[q] = ap[q];
        }
        {
            const uint4* bp = (const uint4*)(brow + chunk * 64 + seg);
            uint4* dp = (uint4*)(Bs + row * 72 + seg);
            #pragma unroll
            for (int q = 0; q < 4; ++q) dp[q] = bp[q];
        }
        __syncthreads();
        #pragma unroll
        for (int kk = 0; kk < 4; ++kk) {
            #pragma unroll
            for (int i = 0; i < 2; ++i)
                wmma::load_matrix_sync(af[i], As + (wm*32 + i*16) * 72 + kk*16, 72);
            #pragma unroll
            for (int j = 0; j < 4; ++j)
                wmma::load_matrix_sync(bf[j], Bs + (wn*64 + j*16) * 72 + kk*16, 72);
            #pragma unroll
            for (int i = 0; i < 2; ++i)
                #pragma unroll
                for (int j = 0; j < 4; ++j)
                    wmma::mma_sync(acc[i][j], af[i], bf[j], acc[i][j]);
        }
        __syncthreads();
    }

    for (int p = 0; p < 2; ++p) {
        if (wn == p) {
            #pragma unroll
            for (int i = 0; i < 2; ++i)
                #pragma unroll
                for (int j = 0; j < 4; ++j)
                    wmma::store_matrix_sync(stage + (wm*32 + i*16) * 68 + j*16,
                                            acc[i][j], 68, wmma::mem_row_major);
        }
        __syncthreads();
        {
            int r2 = tid >> 1, cs = (tid & 1) * 32;
            const float* sp = stage + r2 * 68 + cs;
            uint4 ov[4];
            #pragma unroll
            for (int u = 0; u < 4; ++u) {
                uint32_t pk[4];
                #pragma unroll
                for (int e = 0; e < 4; ++e) {
                    __half2_raw h = __half2_raw(__floats2half2_rn(sp[u*8 + 2*e], sp[u*8 + 2*e + 1]));
                    pk[e] = h.x | ((uint32_t)h.y << 16);
                }
                ov[u] = make_uint4(pk[0], pk[1], pk[2], pk[3]);
            }
            uint4* dp = (uint4*)(g_B_E + (size_t)(c0 + r2) * KPAD + tau0 + p * 64 + cs);
            #pragma unroll
            for (int u = 0; u < 4; ++u) dp[u] = ov[u];
        }
        __syncthreads();
    }
}

// ---------------- conv GEMM (wmma + cp.async double buffer) ----------------
// smem: As0|Bs0|As1|Bs1 (4 x 18432B = 73728) | bias 512
#define CONV_SMEM (73728 + 512)
__global__ __launch_bounds__(256, 2)
void conv_wmma_kernel(const float* __restrict__ conv_b) {
    extern __shared__ char smem[];
    float*  stage = (float*)smem;
    float*  bias  = (float*)(smem + 73728);

    const int tid = threadIdx.x;
    const int wid = tid >> 5;
    const int wm = wid & 3, wn = wid >> 2;
    const int r0 = blockIdx.x * 128;
    const int n0 = blockIdx.y * 128;

    if (tid < 128) bias[tid] = conv_b[n0 + tid];

    const int row = tid >> 1, seg = (tid & 1) * 32;
    const int r = r0 + row, ab = r / 9, am = r - 9 * ab;
    const __half* xrow = g_xhf + (size_t)ab * 1024 + 32 * am;
    const __half* brow = g_B_E + (size_t)(n0 + row) * KPAD;

    const uint32_t sbase = smem_u32(smem);
    const uint32_t aoff = (uint32_t)(row * 72 + seg) * 2;
    // buf s: As at s*36864, Bs at s*36864+18432
    wmma::fragment<wmma::matrix_a, 16, 16, 16, __half, wmma::row_major> af[2];
    wmma::fragment<wmma::matrix_b, 16, 16, 16, __half, wmma::col_major> bf[4];
    wmma::fragment<wmma::accumulator, 16, 16, 16, float> acc[2][4];
    #pragma unroll
    for (int i = 0; i < 2; ++i)
        #pragma unroll
        for (int j = 0; j < 4; ++j)
            wmma::fill_fragment(acc[i][j], 0.0f);

    // prefetch chunk 0 -> buf 0
    {
        uint32_t ad = sbase + aoff, bd = sbase + 18432 + aoff;
        #pragma unroll
        for (int q = 0; q < 4; ++q) cp_async16(ad + q * 16, xrow + seg * 0 + 0 * 64 + seg + q * 8);
        #pragma unroll
        for (int q = 0; q < 4; ++q) cp_async16(bd + q * 16, brow + 0 * 64 + seg + q * 8);
        CP_COMMIT();
    }

    for (int chunk = 0; chunk < 12; ++chunk) {
        if (chunk < 11) {
            uint32_t bufn = ((chunk + 1) & 1) * 36864;
            uint32_t ad = sbase + bufn + aoff, bd = sbase + bufn + 18432 + aoff;
            const __half* xs = xrow + (chunk + 1) * 64 + seg;
            const __half* bs2 = brow + (chunk + 1) * 64 + seg;
            #pragma unroll
            for (int q = 0; q < 4; ++q) cp_async16(ad + q * 16, xs + q * 8);
            #pragma unroll
            for (int q = 0; q < 4; ++q) cp_async16(bd + q * 16, bs2 + q * 8);
            CP_COMMIT();
            CP_WAIT(1);
        } else {
            CP_WAIT(0);
        }
        __syncthreads();
        __half* As = (__half*)(smem + (chunk & 1) * 36864);
        __half* Bs = As + 128 * 72;
        #pragma unroll
        for (int kk = 0; kk < 4; ++kk) {
            #pragma unroll
            for (int i = 0; i < 2; ++i)
                wmma::load_matrix_sync(af[i], As + (wm*32 + i*16) * 72 + kk*16, 72);
            #pragma unroll
            for (int j = 0; j < 4; ++j)
                wmma::load_matrix_sync(bf[j], Bs + (wn*64 + j*16) * 72 + kk*16, 72);
            #pragma unroll
            for (int i = 0; i < 2; ++i)
                #pragma unroll
                for (int j = 0; j < 4; ++j)
                    wmma::mma_sync(acc[i][j], af[i], bf[j], acc[i][j]);
        }
        __syncthreads();
    }

    const int b_first = r0 / 9;
    const int nb = (r0 + 127) / 9 - b_first + 1;
    for (int p = 0; p < 2; ++p) {
        if (wn == p) {
            #pragma unroll
            for (int i = 0; i < 2; ++i)
                #pragma unroll
                for (int j = 0; j < 4; ++j)
                    wmma::store_matrix_sync(stage + (wm*32 + i*16) * 68 + j*16,
                                            acc[i][j], 68, wmma::mem_row_major);
        }
        __syncthreads();
        for (int i = tid; i < nb * 64; i += 256) {
            int bl = i >> 6, col = i & 63;
            int b = b_first + bl;
            int c = n0 + p * 64 + col;
            float bv = bias[p * 64 + col];
            float* dst = g_P2 + (size_t)b * 2304 + c * 9;
            int rb = b * 9;
            #pragma unroll
            for (int m = 0; m < 9; ++m) {
                int rr = rb + m;
                if (rr >= r0 && rr < r0 + 128)
                    dst[m] = stage[(rr - r0) * 68 + col] + bv;
            }
        }
        __syncthreads();
    }
}

// ---------------- u_hat GEMM v3 ----------------
#define UHAT_SMEM (6144 + 6144 + 10240)
__global__ __launch_bounds__(256, 6)
void uhat_gemm_kernel() {
    extern __shared__ char smem[];
    __half* Aw = (__half*)smem;                  // [128][24]
    __half* Bw = (__half*)(smem + 6144);         // [128][24]
    float*  stg = (float*)(smem + 12288);        // per-warp [16][20]

    const int tid = threadIdx.x, wid = tid >> 5, lane = tid & 31;
    const int b0 = blockIdx.x * 128;
    const int g  = blockIdx.y;

    {
        int b_l = tid >> 1, capl = tid & 1;
        int b = b0 + b_l, cap = g * 2 + capl;
        const float4* pp = (const float4*)(g_P2 + (size_t)b * 2304 + cap * 8);
        float4 p0 = pp[0], p1 = pp[1];
        float sn = p0.x*p0.x + p0.y*p0.y + p0.z*p0.z + p0.w*p0.w
                 + p1.x*p1.x + p1.y*p1.y + p1.z*p1.z + p1.w*p1.w;
        float sc = (sn / (1.0f + sn)) * rsqrtf(sn + 1e-8f);
        __half2_raw h0 = __half2_raw(__floats2half2_rn(p0.x*sc, p0.y*sc));
        __half2_raw h1 = __half2_raw(__floats2half2_rn(p0.z*sc, p0.w*sc));
        __half2_raw h2 = __half2_raw(__floats2half2_rn(p1.x*sc, p1.y*sc));
        __half2_raw h3 = __half2_raw(__floats2half2_rn(p1.z*sc, p1.w*sc));
        *(uint4*)(Aw + b_l * 24 + capl * 8) =
            make_uint4(h0.x | ((uint32_t)h0.y << 16), h1.x | ((uint32_t)h1.y << 16),
                       h2.x | ((uint32_t)h2.y << 16), h3.x | ((uint32_t)h3.y << 16));
    }
    {
        int n = tid >> 1, hseg = (tid & 1) * 8;
        uint4 v = *(const uint4*)(g_Bpk + (size_t)g * 2048 + n * 16 + hseg);
        *(uint4*)(Bw + n * 24 + hseg) = v;
    }
    __syncthreads();

    wmma::fragment<wmma::matrix_a, 16, 16, 16, __half, wmma::row_major> af;
    wmma::load_matrix_sync(af, Aw + wid * 16 * 24, 24);
    float* ws = stg + wid * 320;
    const int orow = lane >> 1, ocs = (lane & 1) * 8;
    #pragma unroll
    for (int j = 0; j < 8; ++j) {
        wmma::fragment<wmma::matrix_b, 16, 16, 16, __half, wmma::col_major> bfj;
        wmma::load_matrix_sync(bfj, Bw + j * 16 * 24, 24);
        wmma::fragment<wmma::accumulator, 16, 16, 16, float> acc;
        wmma::fill_fragment(acc, 0.0f);
        wmma::mma_sync(acc, af, bfj, acc);
        wmma::store_matrix_sync(ws, acc, 20, wmma::mem_row_major);
        __syncwarp();
        {
            const float* sp = ws + orow * 20 + ocs;
            uint32_t pk[4];
            #pragma unroll
            for (int e = 0; e < 4; ++e) {
                __half2_raw h = __half2_raw(__floats2half2_rn(sp[2*e], sp[2*e + 1]));
                pk[e] = h.x | ((uint32_t)h.y << 16);
            }
            *(uint4*)(g_UH + (size_t)(b0 + wid * 16 + orow) * 18432 + g * 128 + j * 16 + ocs) =
                make_uint4(pk[0], pk[1], pk[2], pk[3]);
        }
        __syncwarp();
    }
}

// ---------------- routing v4: warp-partitioned half2 s_j, __expf ----------------
// smem: uhh 41472 | bij 4608 | cij 4608 | part 2048 | sjv 256 | vv 256 | snd 16
#define ROUT_SMEM (41472 + 4608 + 4608 + 2048 + 256 + 256 + 16)
__global__ __launch_bounds__(256, 4)
void routing_kernel(float* __restrict__ out, int nB) {
    extern __shared__ char smc[];
    __half* uhh = (__half*)smc;                  // [288][72]
    float* bij  = (float*)(smc + 41472);         // [1152]
    float* cij  = bij + 1152;
    float* part = cij + 1152;                    // [512]
    float* sjv  = part + 512;                    // [64]
    float* vv   = sjv + 64;                      // [64]
    float* snd  = vv + 64;                       // [4]
    const int tid = threadIdx.x;
    const int b = blockIdx.x;

    const uint4* src = (const uint4*)(g_UH + (size_t)b * 18432);
    #pragma unroll
    for (int it = 0; it < 9; ++it) {
        int vi = tid + it * 256;
        uint4 v = src[vi];
        int cc = vi >> 3, seg = (vi & 7) * 8;
        *(uint4*)(uhh + cc * 72 + seg) = v;
    }
    __syncthreads();

    const int prt = tid >> 5, op = tid & 31;     // 8 partitions x 32 half2 lanes
    const int dd  = op >> 3;                     // d for this half2 pair

    for (int r = 0; r < 3; ++r) {
        if (r > 0) {
            for (int j = tid; j < NCAP; j += 256) {
                float b0 = bij[j*4+0], b1 = bij[j*4+1], b2 = bij[j*4+2], b3 = bij[j*4+3];
                float mx = fmaxf(fmaxf(b0, b1), fmaxf(b2, b3));
                float e0 = __expf(b0-mx), e1 = __expf(b1-mx);
                float e2 = __expf(b2-mx), e3 = __expf(b3-mx);
                float inv = 1.0f / (e0 + e1 + e2 + e3);
                cij[j*4+0] = e0*inv; cij[j*4+1] = e1*inv; cij[j*4+2] = e2*inv; cij[j*4+3] = e3*inv;
            }
            __syncthreads();
        }
        {
            float a0 = 0.0f, a1 = 0.0f;
            int cb = prt * 36;
            if (r == 0) {
                for (int cc = cb; cc < cb + 36; ++cc) {
                    float2 f = __half22float2(*(const __half2*)(uhh + cc * 72 + 2 * op));
                    a0 += f.x; a1 += f.y;
                }
                a0 *= 0.25f; a1 *= 0.25f;
            } else {
                for (int cc = cb; cc < cb + 36; ++cc) {
                    float cw = cij[cc * 4 + dd];
                    float2 f = __half22float2(*(const __half2*)(uhh + cc * 72 + 2 * op));
                    a0 += cw * f.x; a1 += cw * f.y;
                }
            }
            part[prt * 64 + 2 * op]     = a0;
            part[prt * 64 + 2 * op + 1] = a1;
        }
        __syncthreads();
        if (tid < 64) {
            float s = 0.0f;
            #pragma unroll
            for (int p = 0; p < 8; ++p) s += part[p * 64 + tid];
            sjv[tid] = s;
        }
        __syncthreads();
        if (tid < 4) {
            float sn = 0.0f;
            #pragma unroll
            for (int o = 0; o < 16; ++o) { float t = sjv[tid*16+o]; sn += t*t; }
            snd[tid] = (sn / (1.0f + sn)) * rsqrtf(sn + 1e-8f);
        }
        __syncthreads();
        if (tid < 64) vv[tid] = sjv[tid] * snd[tid >> 4];
        __syncthreads();
        if (r < 2) {
            for (int i = tid; i < 1152; i += 256) {
                int cc = i >> 2, d2 = i & 3;
                const __half2* up = (const __half2*)(uhh + cc * 72 + d2 * 16);
                const float* vp = vv + d2 * 16;
                float agr = 0.0f;
                #pragma unroll
                for (int e = 0; e < 8; ++e) {
                    float2 f = __half22float2(up[e]);
                    agr += f.x * vp[2*e] + f.y * vp[2*e + 1];
                }
                if (r == 0) bij[i] = agr; else bij[i] += agr;
            }
            __syncthreads();
        }
    }
    if (tid < 4) {
        float sn = 0.0f;
        #pragma unroll
        for (int o = 0; o < 16; ++o) { float t = vv[tid*16+o]; sn += t*t; }
        out[b * 4 + tid] = sqrtf(sn);
    }
    float* out_cij = out + (size_t)nB * 4 + (size_t)b * 1152;
    for (int i = tid; i < 1152; i += 256) out_cij[i] = cij[i];
}

// ---------------- launcher ----------------
extern "C" void kernel_launch(void* const* d_in, const int* in_sizes, int n_in,
                              void* d_out, int out_size) {
    const float* x      = (const float*)d_in[0];
    const float* a      = (const float*)d_in[1];
    const float* w      = (const float*)d_in[2];
    const float* conv_w = (const float*)d_in[3];
    const float* conv_b = (const float*)d_in[4];
    const float* W_caps = (const float*)d_in[5];
    int nB = in_sizes[0] / NPOS;   // 4096

    cudaFuncSetAttribute(conv_wmma_kernel, cudaFuncAttributeMaxDynamicSharedMemorySize, CONV_SMEM);
    cudaFuncSetAttribute(routing_kernel,   cudaFuncAttributeMaxDynamicSharedMemorySize, ROUT_SMEM);

    wav_kernel<<<128, 512>>>(a, w);
    xhf_kernel<<<(int)(((size_t)nB * 1024) / 256), 256>>>(x);
    cwhf_kernel<<<(256 * 2048 + 255) / 256, 256>>>(conv_w);
    w2t_kernel<<<(768 * 2048 + 255) / 256, 256>>>();
    bpk_kernel<<<(144 * 2048 + 255) / 256, 256>>>(W_caps);
    compose_wmma_kernel<<<dim3(2, 6), 256, COMP_SMEM>>>();
    conv_wmma_kernel<<<dim3(nB * 9 / 128, 2), 256, CONV_SMEM>>>(conv_b);
    uhat_gemm_kernel<<<dim3(nB / 128, 144), 256, UHAT_SMEM>>>();
    routing_kernel<<<nB, 256, ROUT_SMEM>>>((float*)d_out, nB);
}

// round 9
// speedup vs baseline: 2.1925x; 1.0278x over previous
#include <cuda_runtime.h>
#include <cuda_fp16.h>
#include <mma.h>
#include <cstdint>

using namespace nvcuda;

#define NPOS  1008
#define KPAD  768
#define NCAP  288

// ---------------- device scratch ----------------
__device__ float  g_wavT[512 * 128];                // wavT[k][o]
__device__ __half g_xhf[(size_t)4096 * 1024];       // x fp16, padded stride 1024 (tail zero)
__device__ __half g_cwhf[256 * 2048];               // conv_w fp16, k-index = o + 128*k2
__device__ __half g_W2T[768 * 2048];                // wav im2col: [tau][o + 128*k2]
__device__ __half g_B_E[256 * KPAD];                // E[c][tau]
__device__ __half g_Bpk[144 * 128 * 16];            // packed block-diag W: [g][n][k]
__device__ float  g_P2[(size_t)4096 * 2304];        // p [b][flat=c*9+m]
__device__ __half g_UH[(size_t)4096 * 18432];       // u_hat [b][cap*64 + d*16 + o]

// ---------------- helpers ----------------
static __device__ __forceinline__ uint32_t smem_u32(const void* p) {
    uint32_t a;
    asm("{ .reg .u64 t; cvta.to.shared.u64 t, %1; cvt.u32.u64 %0, t; }" : "=r"(a) : "l"(p));
    return a;
}
static __device__ __forceinline__ void cp_async16(uint32_t dst, const void* src) {
    asm volatile("cp.async.cg.shared.global [%0], [%1], 16;" :: "r"(dst), "l"(src));
}
#define CP_COMMIT() asm volatile("cp.async.commit_group;" ::: "memory")
#define CP_WAIT(n)  asm volatile("cp.async.wait_group %0;" :: "n"(n) : "memory")

// ---------------- fused precompute: xhf | cwhf | bpk | wav ----------------
// blocks: [0,16384) xhf, [16384,18432) cwhf, [18432,19584) bpk, [19584,19840) wav
__global__ void pre1_kernel(const float* __restrict__ x, const float* __restrict__ a,
                            const float* __restrict__ w, const float* __restrict__ conv_w,
                            const float* __restrict__ Wc) {
    const int bid = blockIdx.x, tid = threadIdx.x;
    if (bid < 16384) {
        size_t i = (size_t)bid * 256 + tid;
        int b = (int)(i >> 10), pos = (int)(i & 1023);
        float v = (pos < NPOS) ? x[(size_t)b * NPOS + pos] : 0.0f;
        g_xhf[i] = __float2half_rn(v);
    } else if (bid < 18432) {
        int i = (bid - 16384) * 256 + tid;
        int c = i >> 11, j = i & 2047;
        int o = j & 127, k2 = j >> 7;
        g_cwhf[i] = __float2half_rn(conv_w[c * 2048 + o * 16 + k2]);
    } else if (bid < 19584) {
        int i = (bid - 18432) * 256 + tid;
        int g = i >> 11, rem = i & 2047;
        int n = rem >> 4, k = rem & 15;
        int capl = n >> 6, np = n & 63;
        int capk = k >> 3, ii = k & 7;
        float v = (capl == capk) ? Wc[(size_t)(2 * g + capl) * 512 + np * 8 + ii] : 0.0f;
        g_Bpk[i] = __float2half_rn(v);
    } else {
        int ob = bid - 19584;                       // 256 blocks: o = ob>>1, k-half = ob&1
        int o = ob >> 1, k = ((ob & 1) << 8) + tid;
        float av = fmaxf(a[o], 1e-5f);
        float t  = fmaf((float)k, 2.0f / 511.0f, -1.0f);
        float ts = t / av;
        g_wavT[k * 128 + o] = cosf(w[o] * t) * expf(-0.5f * ts * ts);
    }
}

__global__ void w2t_kernel() {
    int i = blockIdx.x * 256 + threadIdx.x;
    if (i >= 768 * 2048) return;
    int tau = i >> 11, j = i & 2047;
    int o = j & 127, k2 = j >> 7;
    int k = tau - 16 * k2;
    float v = (k >= 0 && k < 512) ? g_wavT[k * 128 + o] : 0.0f;
    g_W2T[i] = __float2half_rn(v);
}

// ---------------- compose GEMM (wmma): E[256,768] = cwhf x W2T^T, K=2048 ----------------
#define COMP_SMEM 36864
__global__ __launch_bounds__(256, 2)
void compose_wmma_kernel() {
    extern __shared__ char smem[];
    __half* As = (__half*)smem;
    __half* Bs = As + 128 * 72;
    float*  stage = (float*)smem;

    const int tid = threadIdx.x;
    const int wid = tid >> 5;
    const int wm = wid & 3, wn = wid >> 2;
    const int c0   = blockIdx.x * 128;
    const int tau0 = blockIdx.y * 128;

    const int row = tid >> 1, seg = (tid & 1) * 32;
    const __half* arow = g_cwhf + (size_t)(c0 + row) * 2048;
    const __half* brow = g_W2T + (size_t)(tau0 + row) * 2048;

    wmma::fragment<wmma::matrix_a, 16, 16, 16, __half, wmma::row_major> af[2];
    wmma::fragment<wmma::matrix_b, 16, 16, 16, __half, wmma::col_major> bf[4];
    wmma::fragment<wmma::accumulator, 16, 16, 16, float> acc[2][4];
    #pragma unroll
    for (int i = 0; i < 2; ++i)
        #pragma unroll
        for (int j = 0; j < 4; ++j)
            wmma::fill_fragment(acc[i][j], 0.0f);

    for (int chunk = 0; chunk < 32; ++chunk) {
        {
            const uint4* ap = (const uint4*)(arow + chunk * 64 + seg);
            uint4* dp = (uint4*)(As + row * 72 + seg);
            #pragma unroll
            for (int q = 0; q < 4; ++q) dp[q] = ap[q];
        }
        {
            const uint4* bp = (const uint4*)(brow + chunk * 64 + seg);
            uint4* dp = (uint4*)(Bs + row * 72 + seg);
            #pragma unroll
            for (int q = 0; q < 4; ++q) dp[q] = bp[q];
        }
        __syncthreads();
        #pragma unroll
        for (int kk = 0; kk < 4; ++kk) {
            #pragma unroll
            for (int i = 0; i < 2; ++i)
                wmma::load_matrix_sync(af[i], As + (wm*32 + i*16) * 72 + kk*16, 72);
            #pragma unroll
            for (int j = 0; j < 4; ++j)
                wmma::load_matrix_sync(bf[j], Bs + (wn*64 + j*16) * 72 + kk*16, 72);
            #pragma unroll
            for (int i = 0; i < 2; ++i)
                #pragma unroll
                for (int j = 0; j < 4; ++j)
                    wmma::mma_sync(acc[i][j], af[i], bf[j], acc[i][j]);
        }
        __syncthreads();
    }

    for (int p = 0; p < 2; ++p) {
        if (wn == p) {
            #pragma unroll
            for (int i = 0; i < 2; ++i)
                #pragma unroll
                for (int j = 0; j < 4; ++j)
                    wmma::store_matrix_sync(stage + (wm*32 + i*16) * 68 + j*16,
                                            acc[i][j], 68, wmma::mem_row_major);
        }
        __syncthreads();
        {
            int r2 = tid >> 1, cs = (tid & 1) * 32;
            const float* sp = stage + r2 * 68 + cs;
            uint4 ov[4];
            #pragma unroll
            for (int u = 0; u < 4; ++u) {
                uint32_t pk[4];
                #pragma unroll
                for (int e = 0; e < 4; ++e) {
                    __half2_raw h = __half2_raw(__floats2half2_rn(sp[u*8 + 2*e], sp[u*8 + 2*e + 1]));
                    pk[e] = h.x | ((uint32_t)h.y << 16);
                }
                ov[u] = make_uint4(pk[0], pk[1], pk[2], pk[3]);
            }
            uint4* dp = (uint4*)(g_B_E + (size_t)(c0 + r2) * KPAD + tau0 + p * 64 + cs);
            #pragma unroll
            for (int u = 0; u < 4; ++u) dp[u] = ov[u];
        }
        __syncthreads();
    }
}

// ---------------- conv GEMM (wmma + cp.async double buffer, coalesced epilogue) ----------------
// smem: As0|Bs0|As1|Bs1 (73728) reused as stage[128][130]f (66560) | bias 512
#define CONV_SMEM (73728 + 512)
__global__ __launch_bounds__(256, 2)
void conv_wmma_kernel(const float* __restrict__ conv_b) {
    extern __shared__ char smem[];
    float*  stage = (float*)smem;               // [128][130]
    float*  bias  = (float*)(smem + 73728);

    const int tid = threadIdx.x;
    const int wid = tid >> 5;
    const int wm = wid & 3, wn = wid >> 2;
    const int r0 = blockIdx.x * 128;
    const int n0 = blockIdx.y * 128;

    if (tid < 128) bias[tid] = conv_b[n0 + tid];

    const int row = tid >> 1, seg = (tid & 1) * 32;
    const int r = r0 + row, ab = r / 9, am = r - 9 * ab;
    const __half* xrow = g_xhf + (size_t)ab * 1024 + 32 * am;
    const __half* brow = g_B_E + (size_t)(n0 + row) * KPAD;

    const uint32_t sbase = smem_u32(smem);
    const uint32_t aoff = (uint32_t)(row * 72 + seg) * 2;
    wmma::fragment<wmma::matrix_a, 16, 16, 16, __half, wmma::row_major> af[2];
    wmma::fragment<wmma::matrix_b, 16, 16, 16, __half, wmma::col_major> bf[4];
    wmma::fragment<wmma::accumulator, 16, 16, 16, float> acc[2][4];
    #pragma unroll
    for (int i = 0; i < 2; ++i)
        #pragma unroll
        for (int j = 0; j < 4; ++j)
            wmma::fill_fragment(acc[i][j], 0.0f);

    {
        uint32_t ad = sbase + aoff, bd = sbase + 18432 + aoff;
        #pragma unroll
        for (int q = 0; q < 4; ++q) cp_async16(ad + q * 16, xrow + seg + q * 8);
        #pragma unroll
        for (int q = 0; q < 4; ++q) cp_async16(bd + q * 16, brow + seg + q * 8);
        CP_COMMIT();
    }

    for (int chunk = 0; chunk < 12; ++chunk) {
        if (chunk < 11) {
            uint32_t bufn = ((chunk + 1) & 1) * 36864;
            uint32_t ad = sbase + bufn + aoff, bd = sbase + bufn + 18432 + aoff;
            const __half* xs = xrow + (chunk + 1) * 64 + seg;
            const __half* bs2 = brow + (chunk + 1) * 64 + seg;
            #pragma unroll
            for (int q = 0; q < 4; ++q) cp_async16(ad + q * 16, xs + q * 8);
            #pragma unroll
            for (int q = 0; q < 4; ++q) cp_async16(bd + q * 16, bs2 + q * 8);
            CP_COMMIT();
            CP_WAIT(1);
        } else {
            CP_WAIT(0);
        }
        __syncthreads();
        __half* As = (__half*)(smem + (chunk & 1) * 36864);
        __half* Bs = As + 128 * 72;
        #pragma unroll
        for (int kk = 0; kk < 4; ++kk) {
            #pragma unroll
            for (int i = 0; i < 2; ++i)
                wmma::load_matrix_sync(af[i], As + (wm*32 + i*16) * 72 + kk*16, 72);
            #pragma unroll
            for (int j = 0; j < 4; ++j)
                wmma::load_matrix_sync(bf[j], Bs + (wn*64 + j*16) * 72 + kk*16, 72);
            #pragma unroll
            for (int i = 0; i < 2; ++i)
                #pragma unroll
                for (int j = 0; j < 4; ++j)
                    wmma::mma_sync(acc[i][j], af[i], bf[j], acc[i][j]);
        }
        __syncthreads();
    }

    // ---- epilogue: single full-width stage, coalesced P2 writes ----
    #pragma unroll
    for (int i = 0; i < 2; ++i)
        #pragma unroll
        for (int j = 0; j < 4; ++j)
            wmma::store_matrix_sync(stage + (wm*32 + i*16) * 130 + wn*64 + j*16,
                                    acc[i][j], 130, wmma::mem_row_major);
    __syncthreads();

    const int b_first = r0 / 9;
    const int b_last  = (r0 + 127) / 9;
    for (int b = b_first; b <= b_last; ++b) {
        const int rbase = b * 9 - r0;
        float* dst = g_P2 + (size_t)b * 2304 + (size_t)n0 * 9;
        for (int j = tid; j < 1152; j += 256) {
            int cl = j / 9, m = j - 9 * cl;
            int rr = rbase + m;
            if (rr >= 0 && rr < 128)
                dst[j] = stage[rr * 130 + cl] + bias[cl];
        }
    }
}

// ---------------- u_hat GEMM v3 ----------------
#define UHAT_SMEM (6144 + 6144 + 10240)
__global__ __launch_bounds__(256, 6)
void uhat_gemm_kernel() {
    extern __shared__ char smem[];
    __half* Aw = (__half*)smem;                  // [128][24]
    __half* Bw = (__half*)(smem + 6144);         // [128][24]
    float*  stg = (float*)(smem + 12288);        // per-warp [16][20]

    const int tid = threadIdx.x, wid = tid >> 5, lane = tid & 31;
    const int b0 = blockIdx.x * 128;
    const int g  = blockIdx.y;

    {
        int b_l = tid >> 1, capl = tid & 1;
        int b = b0 + b_l, cap = g * 2 + capl;
        const float4* pp = (const float4*)(g_P2 + (size_t)b * 2304 + cap * 8);
        float4 p0 = pp[0], p1 = pp[1];
        float sn = p0.x*p0.x + p0.y*p0.y + p0.z*p0.z + p0.w*p0.w
                 + p1.x*p1.x + p1.y*p1.y + p1.z*p1.z + p1.w*p1.w;
        float sc = (sn / (1.0f + sn)) * rsqrtf(sn + 1e-8f);
        __half2_raw h0 = __half2_raw(__floats2half2_rn(p0.x*sc, p0.y*sc));
        __half2_raw h1 = __half2_raw(__floats2half2_rn(p0.z*sc, p0.w*sc));
        __half2_raw h2 = __half2_raw(__floats2half2_rn(p1.x*sc, p1.y*sc));
        __half2_raw h3 = __half2_raw(__floats2half2_rn(p1.z*sc, p1.w*sc));
        *(uint4*)(Aw + b_l * 24 + capl * 8) =
            make_uint4(h0.x | ((uint32_t)h0.y << 16), h1.x | ((uint32_t)h1.y << 16),
                       h2.x | ((uint32_t)h2.y << 16), h3.x | ((uint32_t)h3.y << 16));
    }
    {
        int n = tid >> 1, hseg = (tid & 1) * 8;
        uint4 v = *(const uint4*)(g_Bpk + (size_t)g * 2048 + n * 16 + hseg);
        *(uint4*)(Bw + n * 24 + hseg) = v;
    }
    __syncthreads();

    wmma::fragment<wmma::matrix_a, 16, 16, 16, __half, wmma::row_major> af;
    wmma::load_matrix_sync(af, Aw + wid * 16 * 24, 24);
    float* ws = stg + wid * 320;
    const int orow = lane >> 1, ocs = (lane & 1) * 8;
    #pragma unroll
    for (int j = 0; j < 8; ++j) {
        wmma::fragment<wmma::matrix_b, 16, 16, 16, __half, wmma::col_major> bfj;
        wmma::load_matrix_sync(bfj, Bw + j * 16 * 24, 24);
        wmma::fragment<wmma::accumulator, 16, 16, 16, float> acc;
        wmma::fill_fragment(acc, 0.0f);
        wmma::mma_sync(acc, af, bfj, acc);
        wmma::store_matrix_sync(ws, acc, 20, wmma::mem_row_major);
        __syncwarp();
        {
            const float* sp = ws + orow * 20 + ocs;
            uint32_t pk[4];
            #pragma unroll
            for (int e = 0; e < 4; ++e) {
                __half2_raw h = __half2_raw(__floats2half2_rn(sp[2*e], sp[2*e + 1]));
                pk[e] = h.x | ((uint32_t)h.y << 16);
            }
            *(uint4*)(g_UH + (size_t)(b0 + wid * 16 + orow) * 18432 + g * 128 + j * 16 + ocs) =
                make_uint4(pk[0], pk[1], pk[2], pk[3]);
        }
        __syncwarp();
    }
}

// ---------------- routing v5: fused reductions ----------------
// smem: uhh 41472 | bij 4608 | cij 4608 | part 2048 | vv 256
#define ROUT_SMEM (41472 + 4608 + 4608 + 2048 + 256)
__global__ __launch_bounds__(256, 4)
void routing_kernel(float* __restrict__ out, int nB) {
    extern __shared__ char smc[];
    __half* uhh = (__half*)smc;                  // [288][72]
    float* bij  = (float*)(smc + 41472);         // [1152]
    float* cij  = bij + 1152;
    float* part = cij + 1152;                    // [512]
    float* vv   = part + 512;                    // [64]
    const int tid = threadIdx.x;
    const int b = blockIdx.x;

    const uint4* src = (const uint4*)(g_UH + (size_t)b * 18432);
    #pragma unroll
    for (int it = 0; it < 9; ++it) {
        int vi = tid + it * 256;
        uint4 v = src[vi];
        int cc = vi >> 3, seg = (vi & 7) * 8;
        *(uint4*)(uhh + cc * 72 + seg) = v;
    }
    __syncthreads();

    const int prt = tid >> 5, op = tid & 31;     // 8 partitions x 32 half2 lanes
    const int dd  = op >> 3;

    for (int r = 0; r < 3; ++r) {
        if (r > 0) {
            for (int j = tid; j < NCAP; j += 256) {
                float b0 = bij[j*4+0], b1 = bij[j*4+1], b2 = bij[j*4+2], b3 = bij[j*4+3];
                float mx = fmaxf(fmaxf(b0, b1), fmaxf(b2, b3));
                float e0 = __expf(b0-mx), e1 = __expf(b1-mx);
                float e2 = __expf(b2-mx), e3 = __expf(b3-mx);
                float inv = 1.0f / (e0 + e1 + e2 + e3);
                cij[j*4+0] = e0*inv; cij[j*4+1] = e1*inv; cij[j*4+2] = e2*inv; cij[j*4+3] = e3*inv;
            }
            __syncthreads();
        }
        {
            float a0 = 0.0f, a1 = 0.0f;
            int cb = prt * 36;
            if (r == 0) {
                for (int cc = cb; cc < cb + 36; ++cc) {
                    float2 f = __half22float2(*(const __half2*)(uhh + cc * 72 + 2 * op));
                    a0 += f.x; a1 += f.y;
                }
                a0 *= 0.25f; a1 *= 0.25f;
            } else {
                for (int cc = cb; cc < cb + 36; ++cc) {
                    float cw = cij[cc * 4 + dd];
                    float2 f = __half22float2(*(const __half2*)(uhh + cc * 72 + 2 * op));
                    a0 += cw * f.x; a1 += cw * f.y;
                }
            }
            part[prt * 64 + 2 * op]     = a0;
            part[prt * 64 + 2 * op + 1] = a1;
        }
        __syncthreads();
        if (tid < 64) {
            float s = 0.0f;
            #pragma unroll
            for (int p = 0; p < 8; ++p) s += part[p * 64 + tid];
            float sq = s * s;
            #pragma unroll
            for (int off = 8; off >= 1; off >>= 1)
                sq += __shfl_xor_sync(0xffffffffu, sq, off);
            float scale = (sq / (1.0f + sq)) * rsqrtf(sq + 1e-8f);
            vv[tid] = s * scale;
        }
        __syncthreads();
        if (r < 2) {
            for (int i = tid; i < 1152; i += 256) {
                int cc = i >> 2, d2 = i & 3;
                const __half2* up = (const __half2*)(uhh + cc * 72 + d2 * 16);
                const float* vp = vv + d2 * 16;
                float agr = 0.0f;
                #pragma unroll
                for (int e = 0; e < 8; ++e) {
                    float2 f = __half22float2(up[e]);
                    agr += f.x * vp[2*e] + f.y * vp[2*e + 1];
                }
                if (r == 0) bij[i] = agr; else bij[i] += agr;
            }
            __syncthreads();
        }
    }
    if (tid < 4) {
        float sn = 0.0f;
        #pragma unroll
        for (int o = 0; o < 16; ++o) { float t = vv[tid*16+o]; sn += t*t; }
        out[b * 4 + tid] = sqrtf(sn);
    }
    float* out_cij = out + (size_t)nB * 4 + (size_t)b * 1152;
    for (int i = tid; i < 1152; i += 256) out_cij[i] = cij[i];
}

// ---------------- launcher ----------------
extern "C" void kernel_launch(void* const* d_in, const int* in_sizes, int n_in,
                              void* d_out, int out_size) {
    const float* x      = (const float*)d_in[0];
    const float* a      = (const float*)d_in[1];
    const float* w      = (const float*)d_in[2];
    const float* conv_w = (const float*)d_in[3];
    const float* conv_b = (const float*)d_in[4];
    const float* W_caps = (const float*)d_in[5];
    int nB = in_sizes[0] / NPOS;   // 4096

    cudaFuncSetAttribute(conv_wmma_kernel, cudaFuncAttributeMaxDynamicSharedMemorySize, CONV_SMEM);
    cudaFuncSetAttribute(routing_kernel,   cudaFuncAttributeMaxDynamicSharedMemorySize, ROUT_SMEM);

    pre1_kernel<<<19840, 256>>>(x, a, w, conv_w, W_caps);
    w2t_kernel<<<6144, 256>>>();
    compose_wmma_kernel<<<dim3(2, 6), 256, COMP_SMEM>>>();
    conv_wmma_kernel<<<dim3(nB * 9 / 128, 2), 256, CONV_SMEM>>>(conv_b);
    uhat_gemm_kernel<<<dim3(nB / 128, 144), 256, UHAT_SMEM>>>();
    routing_kernel<<<nB, 256, ROUT_SMEM>>>((float*)d_out, nB);
}

// round 10
// speedup vs baseline: 2.2409x; 1.0220x over previous
#include <cuda_runtime.h>
#include <cuda_fp16.h>
#include <mma.h>
#include <cstdint>

using namespace nvcuda;

#define NPOS  1008
#define KPAD  768
#define NCAP  288

// ---------------- device scratch ----------------
__device__ float  g_wavT[512 * 128];                // wavT[k][o]
__device__ __half g_xhf[(size_t)4096 * 1024];       // x fp16, padded stride 1024 (tail zero)
__device__ __half g_cwhf[256 * 2048];               // conv_w fp16, k-index = o + 128*k2
__device__ __half g_W2T[768 * 2048];                // wav im2col: [tau][o + 128*k2]
__device__ __half g_B_E[256 * KPAD];                // E[c][tau]
__device__ __half g_Bpk[144 * 128 * 16];            // packed block-diag W: [g][n][k]
__device__ float  g_P2[(size_t)4096 * 2304];        // p [b][flat=c*9+m]
__device__ __half g_UH[(size_t)4096 * 18432];       // u_hat [b][cap*64 + d*16 + o]

// ---------------- helpers ----------------
static __device__ __forceinline__ uint32_t smem_u32(const void* p) {
    uint32_t a;
    asm("{ .reg .u64 t; cvta.to.shared.u64 t, %1; cvt.u32.u64 %0, t; }" : "=r"(a) : "l"(p));
    return a;
}
static __device__ __forceinline__ void cp_async16(uint32_t dst, const void* src) {
    asm volatile("cp.async.cg.shared.global [%0], [%1], 16;" :: "r"(dst), "l"(src));
}
#define CP_COMMIT() asm volatile("cp.async.commit_group;" ::: "memory")
#define CP_WAIT(n)  asm volatile("cp.async.wait_group %0;" :: "n"(n) : "memory")

// ---------------- fused precompute: xhf | cwhf | bpk | wav ----------------
__global__ void pre1_kernel(const float* __restrict__ x, const float* __restrict__ a,
                            const float* __restrict__ w, const float* __restrict__ conv_w,
                            const float* __restrict__ Wc) {
    const int bid = blockIdx.x, tid = threadIdx.x;
    if (bid < 16384) {
        size_t i = (size_t)bid * 256 + tid;
        int b = (int)(i >> 10), pos = (int)(i & 1023);
        float v = (pos < NPOS) ? x[(size_t)b * NPOS + pos] : 0.0f;
        g_xhf[i] = __float2half_rn(v);
    } else if (bid < 18432) {
        int i = (bid - 16384) * 256 + tid;
        int c = i >> 11, j = i & 2047;
        int o = j & 127, k2 = j >> 7;
        g_cwhf[i] = __float2half_rn(conv_w[c * 2048 + o * 16 + k2]);
    } else if (bid < 19584) {
        int i = (bid - 18432) * 256 + tid;
        int g = i >> 11, rem = i & 2047;
        int n = rem >> 4, k = rem & 15;
        int capl = n >> 6, np = n & 63;
        int capk = k >> 3, ii = k & 7;
        float v = (capl == capk) ? Wc[(size_t)(2 * g + capl) * 512 + np * 8 + ii] : 0.0f;
        g_Bpk[i] = __float2half_rn(v);
    } else {
        int ob = bid - 19584;
        int o = ob >> 1, k = ((ob & 1) << 8) + tid;
        float av = fmaxf(a[o], 1e-5f);
        float t  = fmaf((float)k, 2.0f / 511.0f, -1.0f);
        float ts = t / av;
        g_wavT[k * 128 + o] = cosf(w[o] * t) * expf(-0.5f * ts * ts);
    }
}

__global__ void w2t_kernel() {
    int i = blockIdx.x * 256 + threadIdx.x;
    if (i >= 768 * 2048) return;
    int tau = i >> 11, j = i & 2047;
    int o = j & 127, k2 = j >> 7;
    int k = tau - 16 * k2;
    float v = (k >= 0 && k < 512) ? g_wavT[k * 128 + o] : 0.0f;
    g_W2T[i] = __float2half_rn(v);
}

// ---------------- compose GEMM (wmma): E[256,768] = cwhf x W2T^T, K=2048 ----------------
#define COMP_SMEM 36864
__global__ __launch_bounds__(256, 2)
void compose_wmma_kernel() {
    extern __shared__ char smem[];
    __half* As = (__half*)smem;
    __half* Bs = As + 128 * 72;
    float*  stage = (float*)smem;

    const int tid = threadIdx.x;
    const int wid = tid >> 5;
    const int wm = wid & 3, wn = wid >> 2;
    const int c0   = blockIdx.x * 128;
    const int tau0 = blockIdx.y * 128;

    const int row = tid >> 1, seg = (tid & 1) * 32;
    const __half* arow = g_cwhf + (size_t)(c0 + row) * 2048;
    const __half* brow = g_W2T + (size_t)(tau0 + row) * 2048;

    wmma::fragment<wmma::matrix_a, 16, 16, 16, __half, wmma::row_major> af[2];
    wmma::fragment<wmma::matrix_b, 16, 16, 16, __half, wmma::col_major> bf[4];
    wmma::fragment<wmma::accumulator, 16, 16, 16, float> acc[2][4];
    #pragma unroll
    for (int i = 0; i < 2; ++i)
        #pragma unroll
        for (int j = 0; j < 4; ++j)
            wmma::fill_fragment(acc[i][j], 0.0f);

    for (int chunk = 0; chunk < 32; ++chunk) {
        {
            const uint4* ap = (const uint4*)(arow + chunk * 64 + seg);
            uint4* dp = (uint4*)(As + row * 72 + seg);
            #pragma unroll
            for (int q = 0; q < 4; ++q) dp[q] = ap[q];
        }
        {
            const uint4* bp = (const uint4*)(brow + chunk * 64 + seg);
            uint4* dp = (uint4*)(Bs + row * 72 + seg);
            #pragma unroll
            for (int q = 0; q < 4; ++q) dp[q] = bp[q];
        }
        __syncthreads();
        #pragma unroll
        for (int kk = 0; kk < 4; ++kk) {
            #pragma unroll
            for (int i = 0; i < 2; ++i)
                wmma::load_matrix_sync(af[i], As + (wm*32 + i*16) * 72 + kk*16, 72);
            #pragma unroll
            for (int j = 0; j < 4; ++j)
                wmma::load_matrix_sync(bf[j], Bs + (wn*64 + j*16) * 72 + kk*16, 72);
            #pragma unroll
            for (int i = 0; i < 2; ++i)
                #pragma unroll
                for (int j = 0; j < 4; ++j)
                    wmma::mma_sync(acc[i][j], af[i], bf[j], acc[i][j]);
        }
        __syncthreads();
    }

    for (int p = 0; p < 2; ++p) {
        if (wn == p) {
            #pragma unroll
            for (int i = 0; i < 2; ++i)
                #pragma unroll
                for (int j = 0; j < 4; ++j)
                    wmma::store_matrix_sync(stage + (wm*32 + i*16) * 68 + j*16,
                                            acc[i][j], 68, wmma::mem_row_major);
        }
        __syncthreads();
        {
            int r2 = tid >> 1, cs = (tid & 1) * 32;
            const float* sp = stage + r2 * 68 + cs;
            uint4 ov[4];
            #pragma unroll
            for (int u = 0; u < 4; ++u) {
                uint32_t pk[4];
                #pragma unroll
                for (int e = 0; e < 4; ++e) {
                    __half2_raw h = __half2_raw(__floats2half2_rn(sp[u*8 + 2*e], sp[u*8 + 2*e + 1]));
                    pk[e] = h.x | ((uint32_t)h.y << 16);
                }
                ov[u] = make_uint4(pk[0], pk[1], pk[2], pk[3]);
            }
            uint4* dp = (uint4*)(g_B_E + (size_t)(c0 + r2) * KPAD + tau0 + p * 64 + cs);
            #pragma unroll
            for (int u = 0; u < 4; ++u) dp[u] = ov[u];
        }
        __syncthreads();
    }
}

// ---------------- conv GEMM v3: merged N (N=256/CTA), 512 threads, cp.async 2-stage ----------------
// buf: A[128][72]h (18432) + B[256][72]h (36864) = 55296; x2 = 110592; bias[256]f = 1024
#define CONV_SMEM (110592 + 1024)
__global__ __launch_bounds__(512, 1)
void conv_wmma_kernel(const float* __restrict__ conv_b) {
    extern __shared__ char smem[];
    float*  stage = (float*)smem;               // epilogue: [128][130]f
    float*  bias  = (float*)(smem + 110592);    // [256]

    const int tid = threadIdx.x;
    const int wid = tid >> 5;                   // 0..15
    const int wm = wid & 3, wn = wid >> 2;      // wm: 4 x 32 rows, wn: 4 x 64 cols
    const int r0 = blockIdx.x * 128;

    if (tid < 256) bias[tid] = conv_b[tid];

    // A-load mapping: 2 cp/thread
    const int arow_i = tid >> 2, aseg = (tid & 3) * 16;
    const int ar = r0 + arow_i, ab = ar / 9, am = ar - 9 * ab;
    const __half* xrow = g_xhf + (size_t)ab * 1024 + 32 * am + aseg;
    // B-load mapping: 4 cp/thread
    const int brow_i = tid >> 1, bseg = (tid & 1) * 32;
    const __half* brow = g_B_E + (size_t)brow_i * KPAD + bseg;

    const uint32_t sbase = smem_u32(smem);
    const uint32_t aoff = (uint32_t)(arow_i * 72 + aseg) * 2;
    const uint32_t boff = 18432 + (uint32_t)(brow_i * 72 + bseg) * 2;

    wmma::fragment<wmma::matrix_a, 16, 16, 16, __half, wmma::row_major> af[2];
    wmma::fragment<wmma::matrix_b, 16, 16, 16, __half, wmma::col_major> bf[4];
    wmma::fragment<wmma::accumulator, 16, 16, 16, float> acc[2][4];
    #pragma unroll
    for (int i = 0; i < 2; ++i)
        #pragma unroll
        for (int j = 0; j < 4; ++j)
            wmma::fill_fragment(acc[i][j], 0.0f);

    {   // prefetch chunk 0 -> buf 0
        #pragma unroll
        for (int q = 0; q < 2; ++q) cp_async16(sbase + aoff + q * 16, xrow + q * 8);
        #pragma unroll
        for (int q = 0; q < 4; ++q) cp_async16(sbase + boff + q * 16, brow + q * 8);
        CP_COMMIT();
    }

    for (int chunk = 0; chunk < 12; ++chunk) {
        if (chunk < 11) {
            uint32_t bufn = ((chunk + 1) & 1) * 55296;
            const __half* xs  = xrow + (chunk + 1) * 64;
            const __half* bs2 = brow + (chunk + 1) * 64;
            #pragma unroll
            for (int q = 0; q < 2; ++q) cp_async16(sbase + bufn + aoff + q * 16, xs + q * 8);
            #pragma unroll
            for (int q = 0; q < 4; ++q) cp_async16(sbase + bufn + boff + q * 16, bs2 + q * 8);
            CP_COMMIT();
            CP_WAIT(1);
        } else {
            CP_WAIT(0);
        }
        __syncthreads();
        __half* As = (__half*)(smem + (chunk & 1) * 55296);
        __half* Bs = As + 128 * 72;
        #pragma unroll
        for (int kk = 0; kk < 4; ++kk) {
            #pragma unroll
            for (int i = 0; i < 2; ++i)
                wmma::load_matrix_sync(af[i], As + (wm*32 + i*16) * 72 + kk*16, 72);
            #pragma unroll
            for (int j = 0; j < 4; ++j)
                wmma::load_matrix_sync(bf[j], Bs + (wn*64 + j*16) * 72 + kk*16, 72);
            #pragma unroll
            for (int i = 0; i < 2; ++i)
                #pragma unroll
                for (int j = 0; j < 4; ++j)
                    wmma::mma_sync(acc[i][j], af[i], bf[j], acc[i][j]);
        }
        __syncthreads();
    }

    // ---- epilogue: two column-half passes, coalesced P2 writes ----
    const int b_first = r0 / 9;
    const int b_last  = (r0 + 127) / 9;
    for (int p = 0; p < 2; ++p) {
        if ((wn >> 1) == p) {
            #pragma unroll
            for (int i = 0; i < 2; ++i)
                #pragma unroll
                for (int j = 0; j < 4; ++j)
                    wmma::store_matrix_sync(stage + (wm*32 + i*16) * 130 + (wn & 1) * 64 + j*16,
                                            acc[i][j], 130, wmma::mem_row_major);
        }
        __syncthreads();
        for (int b = b_first; b <= b_last; ++b) {
            const int rbase = b * 9 - r0;
            float* dst = g_P2 + (size_t)b * 2304 + p * 1152;
            for (int j = tid; j < 1152; j += 512) {
                int cl = j / 9, m = j - 9 * cl;
                int rr = rbase + m;
                if (rr >= 0 && rr < 128)
                    dst[j] = stage[rr * 130 + cl] + bias[p * 128 + cl];
            }
        }
        __syncthreads();
    }
}

// ---------------- u_hat GEMM v3 ----------------
#define UHAT_SMEM (6144 + 6144 + 10240)
__global__ __launch_bounds__(256, 6)
void uhat_gemm_kernel() {
    extern __shared__ char smem[];
    __half* Aw = (__half*)smem;                  // [128][24]
    __half* Bw = (__half*)(smem + 6144);         // [128][24]
    float*  stg = (float*)(smem + 12288);        // per-warp [16][20]

    const int tid = threadIdx.x, wid = tid >> 5, lane = tid & 31;
    const int b0 = blockIdx.x * 128;
    const int g  = blockIdx.y;

    {
        int b_l = tid >> 1, capl = tid & 1;
        int b = b0 + b_l, cap = g * 2 + capl;
        const float4* pp = (const float4*)(g_P2 + (size_t)b * 2304 + cap * 8);
        float4 p0 = pp[0], p1 = pp[1];
        float sn = p0.x*p0.x + p0.y*p0.y + p0.z*p0.z + p0.w*p0.w
                 + p1.x*p1.x + p1.y*p1.y + p1.z*p1.z + p1.w*p1.w;
        float sc = (sn / (1.0f + sn)) * rsqrtf(sn + 1e-8f);
        __half2_raw h0 = __half2_raw(__floats2half2_rn(p0.x*sc, p0.y*sc));
        __half2_raw h1 = __half2_raw(__floats2half2_rn(p0.z*sc, p0.w*sc));
        __half2_raw h2 = __half2_raw(__floats2half2_rn(p1.x*sc, p1.y*sc));
        __half2_raw h3 = __half2_raw(__floats2half2_rn(p1.z*sc, p1.w*sc));
        *(uint4*)(Aw + b_l * 24 + capl * 8) =
            make_uint4(h0.x | ((uint32_t)h0.y << 16), h1.x | ((uint32_t)h1.y << 16),
                       h2.x | ((uint32_t)h2.y << 16), h3.x | ((uint32_t)h3.y << 16));
    }
    {
        int n = tid >> 1, hseg = (tid & 1) * 8;
        uint4 v = *(const uint4*)(g_Bpk + (size_t)g * 2048 + n * 16 + hseg);
        *(uint4*)(Bw + n * 24 + hseg) = v;
    }
    __syncthreads();

    wmma::fragment<wmma::matrix_a, 16, 16, 16, __half, wmma::row_major> af;
    wmma::load_matrix_sync(af, Aw + wid * 16 * 24, 24);
    float* ws = stg + wid * 320;
    const int orow = lane >> 1, ocs = (lane & 1) * 8;
    #pragma unroll
    for (int j = 0; j < 8; ++j) {
        wmma::fragment<wmma::matrix_b, 16, 16, 16, __half, wmma::col_major> bfj;
        wmma::load_matrix_sync(bfj, Bw + j * 16 * 24, 24);
        wmma::fragment<wmma::accumulator, 16, 16, 16, float> acc;
        wmma::fill_fragment(acc, 0.0f);
        wmma::mma_sync(acc, af, bfj, acc);
        wmma::store_matrix_sync(ws, acc, 20, wmma::mem_row_major);
        __syncwarp();
        {
            const float* sp = ws + orow * 20 + ocs;
            uint32_t pk[4];
            #pragma unroll
            for (int e = 0; e < 4; ++e) {
                __half2_raw h = __half2_raw(__floats2half2_rn(sp[2*e], sp[2*e + 1]));
                pk[e] = h.x | ((uint32_t)h.y << 16);
            }
            *(uint4*)(g_UH + (size_t)(b0 + wid * 16 + orow) * 18432 + g * 128 + j * 16 + ocs) =
                make_uint4(pk[0], pk[1], pk[2], pk[3]);
        }
        __syncwarp();
    }
}

// ---------------- routing v6: transposed cij for vectorized s_j ----------------
// smem: uhh 41472 | bij 4608 | cijT 4*292*4=4672 | part 2048 | vv 256
#define ROUT_SMEM (41472 + 4608 + 4672 + 2048 + 256)
__global__ __launch_bounds__(256, 4)
void routing_kernel(float* __restrict__ out, int nB) {
    extern __shared__ char smc[];
    __half* uhh = (__half*)smc;                  // [288][72]
    float* bij  = (float*)(smc + 41472);         // [1152]
    float* cijT = bij + 1152;                    // [4][292]
    float* part = cijT + 4 * 292;                // [512]
    float* vv   = part + 512;                    // [64]
    const int tid = threadIdx.x;
    const int b = blockIdx.x;

    const uint4* src = (const uint4*)(g_UH + (size_t)b * 18432);
    #pragma unroll
    for (int it = 0; it < 9; ++it) {
        int vi = tid + it * 256;
        uint4 v = src[vi];
        int cc = vi >> 3, seg = (vi & 7) * 8;
        *(uint4*)(uhh + cc * 72 + seg) = v;
    }
    __syncthreads();

    const int prt = tid >> 5, op = tid & 31;     // 8 partitions x 32 half2 lanes
    const int dd  = op >> 3;

    for (int r = 0; r < 3; ++r) {
        if (r > 0) {
            for (int j = tid; j < NCAP; j += 256) {
                float b0 = bij[j*4+0], b1 = bij[j*4+1], b2 = bij[j*4+2], b3 = bij[j*4+3];
                float mx = fmaxf(fmaxf(b0, b1), fmaxf(b2, b3));
                float e0 = __expf(b0-mx), e1 = __expf(b1-mx);
                float e2 = __expf(b2-mx), e3 = __expf(b3-mx);
                float inv = 1.0f / (e0 + e1 + e2 + e3);
                cijT[0*292 + j] = e0*inv; cijT[1*292 + j] = e1*inv;
                cijT[2*292 + j] = e2*inv; cijT[3*292 + j] = e3*inv;
            }
            __syncthreads();
        }
        {
            float a0 = 0.0f, a1 = 0.0f;
            int cb = prt * 36;
            if (r == 0) {
                #pragma unroll 4
                for (int cc = cb; cc < cb + 36; ++cc) {
                    float2 f = __half22float2(*(const __half2*)(uhh + cc * 72 + 2 * op));
                    a0 += f.x; a1 += f.y;
                }
                a0 *= 0.25f; a1 *= 0.25f;
            } else {
                const float* cwp = cijT + dd * 292 + cb;
                #pragma unroll
                for (int q = 0; q < 9; ++q) {
                    float4 cw = *(const float4*)(cwp + q * 4);
                    int cc = cb + q * 4;
                    float2 f0 = __half22float2(*(const __half2*)(uhh + (cc+0) * 72 + 2 * op));
                    float2 f1 = __half22float2(*(const __half2*)(uhh + (cc+1) * 72 + 2 * op));
                    float2 f2 = __half22float2(*(const __half2*)(uhh + (cc+2) * 72 + 2 * op));
                    float2 f3 = __half22float2(*(const __half2*)(uhh + (cc+3) * 72 + 2 * op));
                    a0 += cw.x * f0.x + cw.y * f1.x + cw.z * f2.x + cw.w * f3.x;
                    a1 += cw.x * f0.y + cw.y * f1.y + cw.z * f2.y + cw.w * f3.y;
                }
            }
            part[prt * 64 + 2 * op]     = a0;
            part[prt * 64 + 2 * op + 1] = a1;
        }
        __syncthreads();
        if (tid < 64) {
            float s = 0.0f;
            #pragma unroll
            for (int p = 0; p < 8; ++p) s += part[p * 64 + tid];
            float sq = s * s;
            #pragma unroll
            for (int off = 8; off >= 1; off >>= 1)
                sq += __shfl_xor_sync(0xffffffffu, sq, off);
            float scale = (sq / (1.0f + sq)) * rsqrtf(sq + 1e-8f);
            vv[tid] = s * scale;
        }
        __syncthreads();
        if (r < 2) {
            for (int i = tid; i < 1152; i += 256) {
                int cc = i >> 2, d2 = i & 3;
                const __half2* up = (const __half2*)(uhh + cc * 72 + d2 * 16);
                const float* vp = vv + d2 * 16;
                float agr = 0.0f;
                #pragma unroll
                for (int e = 0; e < 8; ++e) {
                    float2 f = __half22float2(up[e]);
                    agr += f.x * vp[2*e] + f.y * vp[2*e + 1];
                }
                if (r == 0) bij[i] = agr; else bij[i] += agr;
            }
            __syncthreads();
        }
    }
    if (tid < 4) {
        float sn = 0.0f;
        #pragma unroll
        for (int o = 0; o < 16; ++o) { float t = vv[tid*16+o]; sn += t*t; }
        out[b * 4 + tid] = sqrtf(sn);
    }
    float* out_cij = out + (size_t)nB * 4 + (size_t)b * 1152;
    for (int i = tid; i < 1152; i += 256)
        out_cij[i] = cijT[(i & 3) * 292 + (i >> 2)];
}

// ---------------- launcher ----------------
extern "C" void kernel_launch(void* const* d_in, const int* in_sizes, int n_in,
                              void* d_out, int out_size) {
    const float* x      = (const float*)d_in[0];
    const float* a      = (const float*)d_in[1];
    const float* w      = (const float*)d_in[2];
    const float* conv_w = (const float*)d_in[3];
    const float* conv_b = (const float*)d_in[4];
    const float* W_caps = (const float*)d_in[5];
    int nB = in_sizes[0] / NPOS;   // 4096

    cudaFuncSetAttribute(conv_wmma_kernel, cudaFuncAttributeMaxDynamicSharedMemorySize, CONV_SMEM);
    cudaFuncSetAttribute(routing_kernel,   cudaFuncAttributeMaxDynamicSharedMemorySize, ROUT_SMEM);

    pre1_kernel<<<19840, 256>>>(x, a, w, conv_w, W_caps);
    w2t_kernel<<<6144, 256>>>();
    compose_wmma_kernel<<<dim3(2, 6), 256, COMP_SMEM>>>();
    conv_wmma_kernel<<<nB * 9 / 128, 512, CONV_SMEM>>>(conv_b);
    uhat_gemm_kernel<<<dim3(nB / 128, 144), 256, UHAT_SMEM>>>();
    routing_kernel<<<nB, 256, ROUT_SMEM>>>((float*)d_out, nB);
}